// round 2
// baseline (speedup 1.0000x reference)
#include <cuda_runtime.h>
#include <math.h>
#include <stdint.h>

#define N_RAYS 65536
#define T0 128
#define T1 64
#define CC 16
#define WPB 8            // warps per block
#define FULLMASK 0xffffffffu

// scalar-loss accumulators (zeroed by init kernel each launch)
__device__ double g_prop, g_uni, g_bi;

__global__ void nerf_init_acc() { g_prop = 0.0; g_uni = 0.0; g_bi = 0.0; }

__device__ __forceinline__ float nan2num(float x) {
    if (isnan(x)) return 0.0f;
    if (isinf(x)) return x > 0.0f ? 3.4028234663852886e38f : -3.4028234663852886e38f;
    return x;
}
__device__ __forceinline__ float spacing_fn(float x) {
    return x < 1.0f ? 0.5f * x : 1.0f - 1.0f / (2.0f * x);
}
__device__ __forceinline__ float spacing_inv(float x) {
    return x < 0.5f ? 2.0f * x : 1.0f / (2.0f - 2.0f * x);
}
__device__ __forceinline__ float wscan_incl(float x, int lane) {
#pragma unroll
    for (int o = 1; o < 32; o <<= 1) {
        float v = __shfl_up_sync(FULLMASK, x, o);
        if (lane >= o) x += v;
    }
    return x;
}
__device__ __forceinline__ float wreduce(float x) {
#pragma unroll
    for (int o = 16; o; o >>= 1) x += __shfl_xor_sync(FULLMASK, x, o);
    return x;
}
// MERF contraction matching jnp reference (first-max argmax, where-semantics)
__device__ __forceinline__ void contract3(float x, float y, float z,
                                          float& cx, float& cy, float& cz) {
    float ax = fabsf(x), ay = fabsf(y), az = fabsf(z);
    float mag = fmaxf(ax, fmaxf(ay, az));
    int idx = (ax >= ay && ax >= az) ? 0 : ((ay >= az) ? 1 : 2);
    float inv = 1.0f / mag;
    float ss = (2.0f - inv) * inv;
    float sx = (idx == 0) ? ss : inv;
    float sy = (idx == 1) ? ss : inv;
    float sz = (idx == 2) ? ss : inv;
    if (mag < 1.0f) { cx = x; cy = y; cz = z; }
    else            { cx = x * sx; cy = y * sy; cz = z * sz; }
}

__global__ __launch_bounds__(WPB * 32)
void nerf_render_kernel(const float* __restrict__ rays_o,
                        const float* __restrict__ rays_d,
                        const float* __restrict__ aabb,
                        const float* __restrict__ sig_c,
                        const float* __restrict__ sig_f,
                        const float* __restrict__ colors,
                        const float* __restrict__ w_view,
                        const float* __restrict__ b_view,
                        float* __restrict__ out) {
    __shared__ float s_cdf[WPB][T0 + 1];
    __shared__ float s_cw [WPB][T0 + 1];
    __shared__ float s_b1 [WPB][T1 + 1];
    __shared__ float s_rb1[WPB][T1 + 1];
    __shared__ float s_w1 [WPB][T1];

    const int lane = threadIdx.x & 31;
    const int w    = threadIdx.x >> 5;
    const int ray  = blockIdx.x * WPB + w;

    const float ox = rays_o[ray * 3 + 0], oy = rays_o[ray * 3 + 1], oz = rays_o[ray * 3 + 2];
    const float dx = rays_d[ray * 3 + 0], dy = rays_d[ray * 3 + 1], dz = rays_d[ray * 3 + 2];

    // near / far from aabb (reference adds 1e-15 to d)
    float t0x = (aabb[0] - ox) / (dx + 1e-15f), t1x = (aabb[3] - ox) / (dx + 1e-15f);
    float t0y = (aabb[1] - oy) / (dy + 1e-15f), t1y = (aabb[4] - oy) / (dy + 1e-15f);
    float t0z = (aabb[2] - oz) / (dz + 1e-15f), t1z = (aabb[5] - oz) / (dz + 1e-15f);
    float nearv = fmaxf(fmaxf(fminf(t0x, t1x), fminf(t0y, t1y)), fminf(t0z, t1z));
    float farv  = fminf(fminf(fmaxf(t0x, t1x), fmaxf(t0y, t1y)), fmaxf(t0z, t1z));
    bool bad = farv < nearv;
    nearv = fmaxf(bad ? 1e9f : nearv, 0.05f);
    farv  = bad ? 1e9f : farv;
    const float sn = spacing_fn(nearv), sf = spacing_fn(farv);

    // ---- Stage A: coarse weights0, cumsum(w0), cdf --------------------------
    const float4 sg = *(const float4*)(sig_c + (size_t)ray * T0 + 4 * lane);
    float e[5];
#pragma unroll
    for (int q = 0; q < 5; q++) {
        float b = (float)(4 * lane + q) * (1.0f / 128.0f);
        e[q] = spacing_inv(sn * (1.0f - b) + sf * b);
    }
    float ds0 = (e[1] - e[0]) * sg.x;
    float ds1 = (e[2] - e[1]) * sg.y;
    float ds2 = (e[3] - e[2]) * sg.z;
    float ds3 = (e[4] - e[3]) * sg.w;
    float la0 = ds0, la1 = la0 + ds1, la2 = la1 + ds2, la3 = la2 + ds3;
    float scn = wscan_incl(la3, lane);
    float baseA = scn - la3;                      // exclusive prefix of ds before this lane
    float w00 = nan2num((1.0f - expf(-ds0)) * expf(-baseA));
    float w01 = nan2num((1.0f - expf(-ds1)) * expf(-(baseA + la0)));
    float w02 = nan2num((1.0f - expf(-ds2)) * expf(-(baseA + la1)));
    float w03 = nan2num((1.0f - expf(-ds3)) * expf(-(baseA + la2)));

    // cumsum of w0 (for prop loss cw1), with leading 0
    {
        float m0 = w00, m1 = m0 + w01, m2 = m1 + w02, m3 = m2 + w03;
        float sc2 = wscan_incl(m3, lane);
        float b2 = sc2 - m3;
        if (lane == 0) s_cw[w][0] = 0.0f;
        s_cw[w][4 * lane + 1] = b2 + m0;
        s_cw[w][4 * lane + 2] = b2 + m1;
        s_cw[w][4 * lane + 3] = b2 + m2;
        s_cw[w][4 * lane + 4] = b2 + m3;
    }
    // cdf of (w0 + 0.01)
    {
        float p0 = w00 + 0.01f, p1 = w01 + 0.01f, p2 = w02 + 0.01f, p3 = w03 + 0.01f;
        float q0 = p0, q1 = q0 + p1, q2 = q1 + p2, q3 = q2 + p3;
        float sc3 = wscan_incl(q3, lane);
        float b3 = sc3 - q3;
        float total = __shfl_sync(FULLMASK, sc3, 31);
        float inv = 1.0f / total;
        if (lane == 0) s_cdf[w][0] = 0.0f;
        s_cdf[w][4 * lane + 1] = fminf((b3 + q0) * inv, 1.0f);
        s_cdf[w][4 * lane + 2] = fminf((b3 + q1) * inv, 1.0f);
        s_cdf[w][4 * lane + 3] = fminf((b3 + q2) * inv, 1.0f);
        s_cdf[w][4 * lane + 4] = fminf((b3 + q3) * inv, 1.0f);
    }
    __syncwarp();

    // ---- Stage B: inverse-CDF sampling of 65 fine bin edges ------------------
    {
        const float us = 0.5f / 65.0f;
        const float ue = 1.0f - 0.5f / 65.0f;
        const float ustep = (ue - us) / 64.0f;
        for (int i = lane; i < T1 + 1; i += 32) {
            float u = us + (float)i * ustep;
            int lo = 0, hi = T0 + 1;
            while (lo < hi) {
                int mid = (lo + hi) >> 1;
                if (s_cdf[w][mid] <= u) lo = mid + 1; else hi = mid;
            }
            int below = lo - 1; below = below < 0 ? 0 : (below > T0 ? T0 : below);
            int above = lo > T0 ? T0 : lo;
            float c0 = s_cdf[w][below], c1 = s_cdf[w][above];
            float t = (u - c0) / (c1 - c0);
            if (isnan(t)) t = 0.0f;
            t = fminf(fmaxf(t, 0.0f), 1.0f);
            float bb0 = (float)below * (1.0f / 128.0f);
            float bb1 = (float)above * (1.0f / 128.0f);
            float b1v = bb0 + t * (bb1 - bb0);
            s_b1[w][i] = b1v;
            s_rb1[w][i] = spacing_inv(sn * (1.0f - b1v) + sf * b1v);
        }
    }
    __syncwarp();

    // ---- Stage C: fine weights1, weights_sum / depth / f_xyz -----------------
    const float2 sgf = *(const float2*)(sig_f + (size_t)ray * T1 + 2 * lane);
    const int i0 = 2 * lane, i1 = i0 + 1;
    float r0 = s_rb1[w][i0], r1 = s_rb1[w][i1], r2 = s_rb1[w][i1 + 1];
    float dsa = (r1 - r0) * sgf.x;
    float dsb = (r2 - r1) * sgf.y;
    float lca = dsa, lcb = lca + dsb;
    float scc = wscan_incl(lcb, lane);
    float bc = scc - lcb;
    float w1a = nan2num((1.0f - expf(-dsa)) * expf(-bc));
    float w1b = nan2num((1.0f - expf(-dsb)) * expf(-(bc + lca)));
    s_w1[w][i0] = w1a;
    s_w1[w][i1] = w1b;
    float ta = 0.5f * (r0 + r1), tb = 0.5f * (r1 + r2);

    float ws  = w1a + w1b;
    float dep = w1a * ta + w1b * tb;
    float fx, fy, fz;
    {
        float cxa, cya, cza, cxb, cyb, czb;
        contract3(ox + dx * ta, oy + dy * ta, oz + dz * ta, cxa, cya, cza);
        contract3(ox + dx * tb, oy + dy * tb, oz + dz * tb, cxb, cyb, czb);
        fx = w1a * cxa + w1b * cxb;
        fy = w1a * cya + w1b * cyb;
        fz = w1a * cza + w1b * czb;
    }
    ws  = wreduce(ws);
    dep = wreduce(dep);
    fx  = wreduce(fx);
    fy  = wreduce(fy);
    fz  = wreduce(fz);
    __syncwarp();

    // ---- Stage D: colors weighted reduction + view matmul + sigmoid ----------
    {
        const float4* c4 = (const float4*)colors + (size_t)ray * (T1 * CC / 4);
        float4 acc = make_float4(0.f, 0.f, 0.f, 0.f);
#pragma unroll
        for (int it = 0; it < 8; ++it) {
            int f = it * 32 + lane;           // float4 index within the ray's row
            float4 cv = __ldcs(c4 + f);       // streaming: read-once, evict-first
            float wv = s_w1[w][f >> 2];       // t = f/4 (4 float4s per sample)
            acc.x += wv * cv.x; acc.y += wv * cv.y;
            acc.z += wv * cv.z; acc.w += wv * cv.w;
        }
#pragma unroll
        for (int o = 4; o < 32; o <<= 1) {
            acc.x += __shfl_xor_sync(FULLMASK, acc.x, o);
            acc.y += __shfl_xor_sync(FULLMASK, acc.y, o);
            acc.z += __shfl_xor_sync(FULLMASK, acc.z, o);
            acc.w += __shfl_xor_sync(FULLMASK, acc.w, o);
        }
        // every lane now holds the 4-channel group (lane&3): channels 4g..4g+3
        int g = lane & 3;
        float d0 = 0.f, d1 = 0.f, d2 = 0.f;
        float av[4] = {acc.x, acc.y, acc.z, acc.w};
#pragma unroll
        for (int j = 0; j < 4; j++) {
            int c = 4 * g + j;
            float fv = av[j];
            d0 += fv * w_view[c * 3 + 0];
            d1 += fv * w_view[c * 3 + 1];
            d2 += fv * w_view[c * 3 + 2];
        }
#pragma unroll
        for (int o = 1; o < 4; o <<= 1) {
            d0 += __shfl_xor_sync(FULLMASK, d0, o);
            d1 += __shfl_xor_sync(FULLMASK, d1, o);
            d2 += __shfl_xor_sync(FULLMASK, d2, o);
        }
        if (lane < 3) {
            float dv = (lane == 0) ? d0 : ((lane == 1) ? d1 : d2);
            float im = 1.0f / (1.0f + expf(-(dv + b_view[lane]))) + (1.0f - ws);
            out[ray * 3 + lane] = im;
        }
        if (lane == 0) {
            out[3 * N_RAYS + ray] = dep;
            out[4 * N_RAYS + ray * 3 + 0] = fx;
            out[4 * N_RAYS + ray * 3 + 1] = fy;
            out[4 * N_RAYS + ray * 3 + 2] = fz;
        }
    }

    // ---- Stage E: interlevel (proposal) loss --------------------------------
    float prop = 0.0f;
    {
        float bA0 = s_b1[w][i0], bA1 = s_b1[w][i1], bA2 = s_b1[w][i1 + 1];
        // sample i0: lo from b1[i0], hi from b1[i0+1]
        int ilo = (int)floorf(bA0 * 128.0f); ilo = ilo < 0 ? 0 : (ilo > 127 ? 127 : ilo);
        int ihi = (int)floorf(bA1 * 128.0f); ihi = ihi < 0 ? 0 : (ihi > 127 ? 127 : ihi);
        float wseg = s_cw[w][ihi + 1] - s_cw[w][ilo];
        float dlt = fmaxf(w1a - wseg, 0.0f);
        prop += dlt * dlt / (w1a + 1e-8f);
        // sample i1
        ilo = (int)floorf(bA1 * 128.0f); ilo = ilo < 0 ? 0 : (ilo > 127 ? 127 : ilo);
        ihi = (int)floorf(bA2 * 128.0f); ihi = ihi < 0 ? 0 : (ihi > 127 ? 127 : ihi);
        wseg = s_cw[w][ihi + 1] - s_cw[w][ilo];
        dlt = fmaxf(w1b - wseg, 0.0f);
        prop += dlt * dlt / (w1b + 1e-8f);
    }

    // ---- Stage F: efficient distortion loss ---------------------------------
    float uni, bi;
    {
        float bA0 = s_b1[w][i0], bA1 = s_b1[w][i1], bA2 = s_b1[w][i1 + 1];
        float inta = bA1 - bA0, intb = bA2 - bA1;
        float mida = bA0 + inta * 0.5f, midb = bA1 + intb * 0.5f;
        uni = inta * w1a * w1a + intb * w1b * w1b;
        float wma = w1a * mida, wmb = w1b * midb;
        // exclusive cumsums of w1 and w1*m
        float lw = w1a + w1b;
        float siW = wscan_incl(lw, lane);
        float exW_a = siW - lw;            // exclusive at i0
        float exW_b = exW_a + w1a;         // exclusive at i1
        float lm = wma + wmb;
        float siM = wscan_incl(lm, lane);
        float exM_a = siM - lm;
        float exM_b = exM_a + wma;
        bi = wma * exW_a - w1a * exM_a + wmb * exW_b - w1b * exM_b;
    }

    prop = wreduce(prop);
    uni  = wreduce(uni);
    bi   = wreduce(bi);
    if (lane == 0) {
        atomicAdd(&g_prop, (double)prop);
        atomicAdd(&g_uni,  (double)uni);
        atomicAdd(&g_bi,   (double)bi);
    }
}

__global__ void nerf_finalize(float* __restrict__ out) {
    out[7 * N_RAYS]     = (float)(g_prop / ((double)N_RAYS * (double)T1));
    out[7 * N_RAYS + 1] = (float)(g_uni / (3.0 * (double)N_RAYS) +
                                  2.0 * g_bi / (double)N_RAYS);
}

extern "C" void kernel_launch(void* const* d_in, const int* in_sizes, int n_in,
                              void* d_out, int out_size) {
    const float* rays_o = (const float*)d_in[0];
    const float* rays_d = (const float*)d_in[1];
    const float* aabb   = (const float*)d_in[2];
    const float* sig_c  = (const float*)d_in[3];
    const float* sig_f  = (const float*)d_in[4];
    const float* colors = (const float*)d_in[5];
    const float* w_view = (const float*)d_in[6];
    const float* b_view = (const float*)d_in[7];
    float* out = (float*)d_out;

    nerf_init_acc<<<1, 1>>>();
    nerf_render_kernel<<<N_RAYS / WPB, WPB * 32>>>(
        rays_o, rays_d, aabb, sig_c, sig_f, colors, w_view, b_view, out);
    nerf_finalize<<<1, 1>>>(out);
}

// round 3
// speedup vs baseline: 1.4124x; 1.4124x over previous
#include <cuda_runtime.h>
#include <math.h>
#include <stdint.h>

#define N_RAYS 65536
#define T0 128
#define T1 64
#define WPB 8
#define NBLOCKS (N_RAYS / WPB)   // 8192
#define FULLMASK 0xffffffffu

// per-block loss partials (always fully overwritten each launch)
__device__ float g_part[3 * NBLOCKS];

__device__ __forceinline__ float frcp(float x) { return __fdividef(1.0f, x); }
__device__ __forceinline__ float spacing_fn(float x) {
    return x < 1.0f ? 0.5f * x : 1.0f - 0.5f * frcp(x);
}
__device__ __forceinline__ float spacing_inv(float x) {
    return x < 0.5f ? 2.0f * x : frcp(2.0f - 2.0f * x);
}
__device__ __forceinline__ float wscan_incl(float x, int lane) {
#pragma unroll
    for (int o = 1; o < 32; o <<= 1) {
        float v = __shfl_up_sync(FULLMASK, x, o);
        if (lane >= o) x += v;
    }
    return x;
}
__device__ __forceinline__ float wreduce(float x) {
#pragma unroll
    for (int o = 16; o; o >>= 1) x += __shfl_xor_sync(FULLMASK, x, o);
    return x;
}
// MERF contraction matching jnp reference (first-max argmax, where-semantics)
__device__ __forceinline__ void contract3(float x, float y, float z,
                                          float& cx, float& cy, float& cz) {
    float ax = fabsf(x), ay = fabsf(y), az = fabsf(z);
    float mag = fmaxf(ax, fmaxf(ay, az));
    int idx = (ax >= ay && ax >= az) ? 0 : ((ay >= az) ? 1 : 2);
    float inv = frcp(mag);
    float ss = (2.0f - inv) * inv;
    float sx = (idx == 0) ? ss : inv;
    float sy = (idx == 1) ? ss : inv;
    float sz = (idx == 2) ? ss : inv;
    if (mag < 1.0f) { cx = x; cy = y; cz = z; }
    else            { cx = x * sx; cy = y * sy; cz = z * sz; }
}

__global__ __launch_bounds__(WPB * 32, 4)
void nerf_render_kernel(const float* __restrict__ rays_o,
                        const float* __restrict__ rays_d,
                        const float* __restrict__ aabb,
                        const float* __restrict__ sig_c,
                        const float* __restrict__ sig_f,
                        const float* __restrict__ colors,
                        const float* __restrict__ w_view,
                        const float* __restrict__ b_view,
                        float* __restrict__ out) {
    __shared__ float  s_cw [WPB][T0 + 1];
    __shared__ float  s_b1 [WPB][T1 + 1];
    __shared__ float  s_rb1[WPB][T1 + 1];
    __shared__ float  s_w1 [WPB][T1];
    __shared__ float4 s_col[WPB][T1 * 4];    // 64 samples x 16 ch = 256 float4 / warp
    __shared__ float  s_loss[3][WPB];

    const int lane = threadIdx.x & 31;
    const int w    = threadIdx.x >> 5;
    const int ray  = blockIdx.x * WPB + w;

    // ---- prefetch colors (256 float4 per ray) into shared via cp.async ------
    {
        const float4* c4 = (const float4*)colors + (size_t)ray * 256;
        uint32_t sbase = (uint32_t)__cvta_generic_to_shared(&s_col[w][0]);
#pragma unroll
        for (int it = 0; it < 8; ++it) {
            int f = it * 32 + lane;
            asm volatile("cp.async.cg.shared.global [%0], [%1], 16;\n"
                         :: "r"(sbase + f * 16), "l"(c4 + f));
        }
        asm volatile("cp.async.commit_group;\n");
    }
    // early sigma loads (overlap with setup math)
    const float4 sg  = *(const float4*)(sig_c + (size_t)ray * T0 + 4 * lane);
    const float2 sgf = *(const float2*)(sig_f + (size_t)ray * T1 + 2 * lane);

    const float ox = rays_o[ray * 3 + 0], oy = rays_o[ray * 3 + 1], oz = rays_o[ray * 3 + 2];
    const float dx = rays_d[ray * 3 + 0], dy = rays_d[ray * 3 + 1], dz = rays_d[ray * 3 + 2];

    // near / far from aabb (reference adds 1e-15 to d)
    float rx = frcp(dx + 1e-15f), ry = frcp(dy + 1e-15f), rz = frcp(dz + 1e-15f);
    float t0x = (aabb[0] - ox) * rx, t1x = (aabb[3] - ox) * rx;
    float t0y = (aabb[1] - oy) * ry, t1y = (aabb[4] - oy) * ry;
    float t0z = (aabb[2] - oz) * rz, t1z = (aabb[5] - oz) * rz;
    float nearv = fmaxf(fmaxf(fminf(t0x, t1x), fminf(t0y, t1y)), fminf(t0z, t1z));
    float farv  = fminf(fminf(fmaxf(t0x, t1x), fmaxf(t0y, t1y)), fmaxf(t0z, t1z));
    bool bad = farv < nearv;
    nearv = fmaxf(bad ? 1e9f : nearv, 0.05f);
    farv  = bad ? 1e9f : farv;
    const float sn = spacing_fn(nearv), sf = spacing_fn(farv);

    // ---- Stage A: coarse weights0 (telescoped), cumsum(w0), implicit cdf ----
    float e[5];
#pragma unroll
    for (int q = 0; q < 5; q++) {
        float b = (float)(4 * lane + q) * (1.0f / 128.0f);
        e[q] = spacing_inv(sn * (1.0f - b) + sf * b);
    }
    float ds0 = (e[1] - e[0]) * sg.x;
    float ds1 = (e[2] - e[1]) * sg.y;
    float ds2 = (e[3] - e[2]) * sg.z;
    float ds3 = (e[4] - e[3]) * sg.w;
    float la0 = ds0, la1 = la0 + ds1, la2 = la1 + ds2, la3 = la2 + ds3;
    float scn = wscan_incl(la3, lane);
    float baseA = scn - la3;                      // exclusive prefix of ds
    float E0 = __expf(-baseA);
    float E1 = __expf(-(baseA + la0));
    float E2 = __expf(-(baseA + la1));
    float E3 = __expf(-(baseA + la2));
    float E4 = __expf(-(baseA + la3));
    float w00 = fmaxf(E0 - E1, 0.0f);             // fmaxf also maps NaN -> 0
    float w01 = fmaxf(E1 - E2, 0.0f);
    float w02 = fmaxf(E2 - E3, 0.0f);
    float w03 = fmaxf(E3 - E4, 0.0f);

    float invT;
    {
        float m0 = w00, m1 = m0 + w01, m2 = m1 + w02, m3 = m2 + w03;
        float sc2 = wscan_incl(m3, lane);
        float b2 = sc2 - m3;
        if (lane == 0) s_cw[w][0] = 0.0f;
        s_cw[w][4 * lane + 1] = b2 + m0;
        s_cw[w][4 * lane + 2] = b2 + m1;
        s_cw[w][4 * lane + 3] = b2 + m2;
        s_cw[w][4 * lane + 4] = b2 + m3;
        float total = __shfl_sync(FULLMASK, sc2, 31) + 0.01f * 128.0f;
        invT = frcp(total);
    }
    __syncwarp();

    // ---- Stage B: inverse-CDF sampling; cdf(k)=min((cw[k]+0.01k)*invT,1) ----
    for (int i = lane; i < T1 + 1; i += 32) {
        float u = ((float)i + 0.5f) * (1.0f / 65.0f);
        int lo = 1, hi = T0 + 1;                  // cdf[0]=0 < u always
        while (lo < hi) {
            int mid = (lo + hi) >> 1;
            float cm = fminf((s_cw[w][mid] + 0.01f * (float)mid) * invT, 1.0f);
            if (cm <= u) lo = mid + 1; else hi = mid;
        }
        int below = lo - 1;
        int above = lo > T0 ? T0 : lo;
        float c0 = fminf((s_cw[w][below] + 0.01f * (float)below) * invT, 1.0f);
        float c1 = fminf((s_cw[w][above] + 0.01f * (float)above) * invT, 1.0f);
        float t = __fdividef(u - c0, c1 - c0);
        if (isnan(t)) t = 0.0f;
        t = fminf(fmaxf(t, 0.0f), 1.0f);
        float b1v = ((float)below + t * (float)(above - below)) * (1.0f / 128.0f);
        s_b1[w][i] = b1v;
        s_rb1[w][i] = spacing_inv(sn * (1.0f - b1v) + sf * b1v);
    }
    __syncwarp();

    // ---- Stage C: fine weights1, weights_sum / depth / f_xyz ----------------
    const int i0 = 2 * lane, i1 = i0 + 1;
    float r0 = s_rb1[w][i0], r1 = s_rb1[w][i1], r2 = s_rb1[w][i1 + 1];
    float dsa = (r1 - r0) * sgf.x;
    float dsb = (r2 - r1) * sgf.y;
    float lca = dsa, lcb = lca + dsb;
    float scc = wscan_incl(lcb, lane);
    float bc = scc - lcb;
    float Ea = __expf(-bc);
    float Eb = __expf(-(bc + lca));
    float Ec = __expf(-(bc + lcb));
    float w1a = fmaxf(Ea - Eb, 0.0f);
    float w1b = fmaxf(Eb - Ec, 0.0f);
    s_w1[w][i0] = w1a;
    s_w1[w][i1] = w1b;
    float ta = 0.5f * (r0 + r1), tb = 0.5f * (r1 + r2);

    float ws  = w1a + w1b;
    float dep = w1a * ta + w1b * tb;
    float fx, fy, fz;
    {
        float cxa, cya, cza, cxb, cyb, czb;
        contract3(ox + dx * ta, oy + dy * ta, oz + dz * ta, cxa, cya, cza);
        contract3(ox + dx * tb, oy + dy * tb, oz + dz * tb, cxb, cyb, czb);
        fx = w1a * cxa + w1b * cxb;
        fy = w1a * cya + w1b * cyb;
        fz = w1a * cza + w1b * czb;
    }
    ws  = wreduce(ws);
    dep = wreduce(dep);
    fx  = wreduce(fx);
    fy  = wreduce(fy);
    fz  = wreduce(fz);
    if (lane == 0) {
        out[3 * N_RAYS + ray] = dep;
        out[4 * N_RAYS + ray * 3 + 0] = fx;
        out[4 * N_RAYS + ray * 3 + 1] = fy;
        out[4 * N_RAYS + ray * 3 + 2] = fz;
    }

    // ---- Stage E: interlevel (proposal) loss --------------------------------
    float prop;
    {
        float bA0 = s_b1[w][i0], bA1 = s_b1[w][i1], bA2 = s_b1[w][i1 + 1];
        int ilo = (int)floorf(bA0 * 128.0f); ilo = ilo < 0 ? 0 : (ilo > 127 ? 127 : ilo);
        int ihi = (int)floorf(bA1 * 128.0f); ihi = ihi < 0 ? 0 : (ihi > 127 ? 127 : ihi);
        float wseg = s_cw[w][ihi + 1] - s_cw[w][ilo];
        float dlt = fmaxf(w1a - wseg, 0.0f);
        prop = dlt * dlt * frcp(w1a + 1e-8f);
        ilo = (int)floorf(bA1 * 128.0f); ilo = ilo < 0 ? 0 : (ilo > 127 ? 127 : ilo);
        ihi = (int)floorf(bA2 * 128.0f); ihi = ihi < 0 ? 0 : (ihi > 127 ? 127 : ihi);
        wseg = s_cw[w][ihi + 1] - s_cw[w][ilo];
        dlt = fmaxf(w1b - wseg, 0.0f);
        prop += dlt * dlt * frcp(w1b + 1e-8f);
    }

    // ---- Stage F: efficient distortion loss ---------------------------------
    float uni, bi;
    {
        float bA0 = s_b1[w][i0], bA1 = s_b1[w][i1], bA2 = s_b1[w][i1 + 1];
        float inta = bA1 - bA0, intb = bA2 - bA1;
        float mida = bA0 + inta * 0.5f, midb = bA1 + intb * 0.5f;
        uni = inta * w1a * w1a + intb * w1b * w1b;
        float wma = w1a * mida, wmb = w1b * midb;
        float lw = w1a + w1b;
        float lm = wma + wmb;
        float siW = wscan_incl(lw, lane);     // independent scans: ILP-2
        float siM = wscan_incl(lm, lane);
        float exW_a = siW - lw, exW_b = exW_a + w1a;
        float exM_a = siM - lm, exM_b = exM_a + wma;
        bi = wma * exW_a - w1a * exM_a + wmb * exW_b - w1b * exM_b;
    }
    prop = wreduce(prop);
    uni  = wreduce(uni);
    bi   = wreduce(bi);
    if (lane == 0) {
        s_loss[0][w] = prop;
        s_loss[1][w] = uni;
        s_loss[2][w] = bi;
    }

    // ---- Stage D: colors weighted reduction (from prefetched smem) ----------
    {
        asm volatile("cp.async.wait_group 0;\n");
        __syncwarp();
        float4 acc = make_float4(0.f, 0.f, 0.f, 0.f);
#pragma unroll
        for (int it = 0; it < 8; ++it) {
            int f = it * 32 + lane;
            float4 cv = s_col[w][f];
            float wv = s_w1[w][f >> 2];
            acc.x += wv * cv.x; acc.y += wv * cv.y;
            acc.z += wv * cv.z; acc.w += wv * cv.w;
        }
#pragma unroll
        for (int o = 4; o < 32; o <<= 1) {
            acc.x += __shfl_xor_sync(FULLMASK, acc.x, o);
            acc.y += __shfl_xor_sync(FULLMASK, acc.y, o);
            acc.z += __shfl_xor_sync(FULLMASK, acc.z, o);
            acc.w += __shfl_xor_sync(FULLMASK, acc.w, o);
        }
        int g = lane & 3;                 // channel group 4g..4g+3
        float d0 = 0.f, d1 = 0.f, d2 = 0.f;
        float av[4] = {acc.x, acc.y, acc.z, acc.w};
#pragma unroll
        for (int j = 0; j < 4; j++) {
            int c = 4 * g + j;
            d0 += av[j] * w_view[c * 3 + 0];
            d1 += av[j] * w_view[c * 3 + 1];
            d2 += av[j] * w_view[c * 3 + 2];
        }
#pragma unroll
        for (int o = 1; o < 4; o <<= 1) {
            d0 += __shfl_xor_sync(FULLMASK, d0, o);
            d1 += __shfl_xor_sync(FULLMASK, d1, o);
            d2 += __shfl_xor_sync(FULLMASK, d2, o);
        }
        if (lane < 3) {
            float dv = (lane == 0) ? d0 : ((lane == 1) ? d1 : d2);
            float im = frcp(1.0f + __expf(-(dv + b_view[lane]))) + (1.0f - ws);
            out[ray * 3 + lane] = im;
        }
    }

    // ---- per-block loss partials -------------------------------------------
    __syncthreads();
    if (threadIdx.x < 3) {
        float s = 0.0f;
#pragma unroll
        for (int j = 0; j < WPB; j++) s += s_loss[threadIdx.x][j];
        g_part[threadIdx.x * NBLOCKS + blockIdx.x] = s;
    }
}

__global__ void nerf_finalize(float* __restrict__ out) {
    __shared__ double sd[256];
    const int tid = threadIdx.x;
    double r[3];
#pragma unroll
    for (int c = 0; c < 3; c++) {
        double a = 0.0;
        for (int i = tid; i < NBLOCKS; i += 256) a += (double)g_part[c * NBLOCKS + i];
        sd[tid] = a;
        __syncthreads();
        for (int s = 128; s > 0; s >>= 1) {
            if (tid < s) sd[tid] += sd[tid + s];
            __syncthreads();
        }
        r[c] = sd[0];
        __syncthreads();
    }
    if (tid == 0) {
        out[7 * N_RAYS]     = (float)(r[0] / ((double)N_RAYS * (double)T1));
        out[7 * N_RAYS + 1] = (float)(r[1] / (3.0 * (double)N_RAYS) +
                                      2.0 * r[2] / (double)N_RAYS);
    }
}

extern "C" void kernel_launch(void* const* d_in, const int* in_sizes, int n_in,
                              void* d_out, int out_size) {
    const float* rays_o = (const float*)d_in[0];
    const float* rays_d = (const float*)d_in[1];
    const float* aabb   = (const float*)d_in[2];
    const float* sig_c  = (const float*)d_in[3];
    const float* sig_f  = (const float*)d_in[4];
    const float* colors = (const float*)d_in[5];
    const float* w_view = (const float*)d_in[6];
    const float* b_view = (const float*)d_in[7];
    float* out = (float*)d_out;

    nerf_render_kernel<<<NBLOCKS, WPB * 32>>>(
        rays_o, rays_d, aabb, sig_c, sig_f, colors, w_view, b_view, out);
    nerf_finalize<<<1, 256>>>(out);
}

// round 5
// speedup vs baseline: 1.6735x; 1.1848x over previous
#include <cuda_runtime.h>
#include <math.h>
#include <stdint.h>

#define N_RAYS 65536
#define T0 128
#define T1 64
#define WPB 8
#define NBLOCKS (N_RAYS / WPB)   // 8192
#define FULLMASK 0xffffffffu

// cross-block loss accumulators; zero at load, reset by last block each launch
__device__ double g_acc[3];
__device__ unsigned int g_cnt;

__device__ __forceinline__ float frcp(float x) { return __fdividef(1.0f, x); }
__device__ __forceinline__ float spacing_fn(float x) {
    return x < 1.0f ? 0.5f * x : 1.0f - 0.5f * frcp(x);
}
__device__ __forceinline__ float spacing_inv(float x) {
    return x < 0.5f ? 2.0f * x : frcp(2.0f - 2.0f * x);
}
__device__ __forceinline__ float wscan_incl(float x, int lane) {
#pragma unroll
    for (int o = 1; o < 32; o <<= 1) {
        float v = __shfl_up_sync(FULLMASK, x, o);
        if (lane >= o) x += v;
    }
    return x;
}
__device__ __forceinline__ float wreduce(float x) {
#pragma unroll
    for (int o = 16; o; o >>= 1) x += __shfl_xor_sync(FULLMASK, x, o);
    return x;
}
// MERF contraction matching jnp reference
__device__ __forceinline__ void contract3(float x, float y, float z,
                                          float& cx, float& cy, float& cz) {
    float ax = fabsf(x), ay = fabsf(y), az = fabsf(z);
    float mag = fmaxf(ax, fmaxf(ay, az));
    int idx = (ax >= ay && ax >= az) ? 0 : ((ay >= az) ? 1 : 2);
    float inv = frcp(mag);
    float ss = (2.0f - inv) * inv;
    float sx = (idx == 0) ? ss : inv;
    float sy = (idx == 1) ? ss : inv;
    float sz = (idx == 2) ? ss : inv;
    if (mag < 1.0f) { cx = x; cy = y; cz = z; }
    else            { cx = x * sx; cy = y * sy; cz = z * sz; }
}
__device__ __forceinline__ float ugrid(int i) {
    return ((float)i + 0.5f) * (1.0f / 65.0f);
}

__global__ __launch_bounds__(WPB * 32, 4)
void nerf_render_kernel(const float* __restrict__ rays_o,
                        const float* __restrict__ rays_d,
                        const float* __restrict__ aabb,
                        const float* __restrict__ sig_c,
                        const float* __restrict__ sig_f,
                        const float* __restrict__ colors,
                        const float* __restrict__ w_view,
                        const float* __restrict__ b_view,
                        float* __restrict__ out) {
    __shared__ float  s_cw [WPB][T0 + 1];
    __shared__ int    s_ind[WPB][T1 + 1];
    __shared__ float  s_b1 [WPB][T1 + 1];
    __shared__ float  s_rb1[WPB][T1 + 1];
    __shared__ float  s_w1 [WPB][T1];
    __shared__ float4 s_col[WPB][T1 * 4];
    __shared__ float  s_loss[3][WPB];

    const int lane = threadIdx.x & 31;
    const int w    = threadIdx.x >> 5;
    const int ray  = blockIdx.x * WPB + w;

    // ---- prefetch colors (256 float4 per ray) into shared via cp.async ------
    {
        const float4* c4 = (const float4*)colors + (size_t)ray * 256;
        uint32_t sbase = (uint32_t)__cvta_generic_to_shared(&s_col[w][0]);
#pragma unroll
        for (int it = 0; it < 8; ++it) {
            int f = it * 32 + lane;
            asm volatile("cp.async.cg.shared.global [%0], [%1], 16;\n"
                         :: "r"(sbase + f * 16), "l"(c4 + f));
        }
        asm volatile("cp.async.commit_group;\n");
    }
    const float4 sg  = *(const float4*)(sig_c + (size_t)ray * T0 + 4 * lane);
    const float2 sgf = *(const float2*)(sig_f + (size_t)ray * T1 + 2 * lane);

    const float ox = rays_o[ray * 3 + 0], oy = rays_o[ray * 3 + 1], oz = rays_o[ray * 3 + 2];
    const float dx = rays_d[ray * 3 + 0], dy = rays_d[ray * 3 + 1], dz = rays_d[ray * 3 + 2];

    float rx = frcp(dx + 1e-15f), ry = frcp(dy + 1e-15f), rz = frcp(dz + 1e-15f);
    float t0x = (aabb[0] - ox) * rx, t1x = (aabb[3] - ox) * rx;
    float t0y = (aabb[1] - oy) * ry, t1y = (aabb[4] - oy) * ry;
    float t0z = (aabb[2] - oz) * rz, t1z = (aabb[5] - oz) * rz;
    float nearv = fmaxf(fmaxf(fminf(t0x, t1x), fminf(t0y, t1y)), fminf(t0z, t1z));
    float farv  = fminf(fminf(fmaxf(t0x, t1x), fmaxf(t0y, t1y)), fmaxf(t0z, t1z));
    bool bad = farv < nearv;
    nearv = fmaxf(bad ? 1e9f : nearv, 0.05f);
    farv  = bad ? 1e9f : farv;
    const float sn = spacing_fn(nearv), sf = spacing_fn(farv);

    // ---- Stage A: coarse transmittance; cw[k] = 1 - E_k (telescoped) --------
    float e[5];
#pragma unroll
    for (int q = 0; q < 5; q++) {
        float b = (float)(4 * lane + q) * (1.0f / 128.0f);
        e[q] = spacing_inv(sn * (1.0f - b) + sf * b);
    }
    float ds0 = (e[1] - e[0]) * sg.x;
    float ds1 = (e[2] - e[1]) * sg.y;
    float ds2 = (e[3] - e[2]) * sg.z;
    float ds3 = (e[4] - e[3]) * sg.w;
    float la0 = ds0, la1 = la0 + ds1, la2 = la1 + ds2, la3 = la2 + ds3;
    float scn = wscan_incl(la3, lane);
    float baseA = scn - la3;                 // cum ds at k = 4*lane
    float E1 = __expf(-(baseA + la0));
    float E2 = __expf(-(baseA + la1));
    float E3 = __expf(-(baseA + la2));
    float E4 = __expf(-(baseA + la3));
    if (lane == 0) s_cw[w][0] = 0.0f;
    s_cw[w][4 * lane + 1] = 1.0f - E1;
    s_cw[w][4 * lane + 2] = 1.0f - E2;
    s_cw[w][4 * lane + 3] = 1.0f - E3;
    s_cw[w][4 * lane + 4] = 1.0f - E4;
    float invT;
    {
        float Elast = __shfl_sync(FULLMASK, E4, 31);
        invT = frcp((1.0f - Elast) + 0.01f * 128.0f);
    }
    __syncwarp();   // s_cw visible to all lanes (single source of truth for cdf)

    // ---- Stage B1: scatter sample->bin index table --------------------------
    // cdf(k) = min((s_cw[k] + 0.01k) * invT, 1). The +0.01k term makes cdf
    // STRICTLY increasing (step >= 0.01*invT >> float noise), and every lane
    // derives c(k) from the SAME shared-memory bits, so boundaries agree
    // bitwise across lanes: the fill is gap-free and write-once.
    {
        int gq[5];
#pragma unroll
        for (int q = 0; q < 5; q++) {
            int k = 4 * lane + q;
            float c = fminf((s_cw[w][k] + 0.01f * (float)k) * invT, 1.0f);
            int gi = (int)ceilf(c * 65.0f - 0.5f);
            gi = gi < 0 ? 0 : (gi > 65 ? 65 : gi);
            while (gi > 0  && c <= ugrid(gi - 1)) --gi;   // exact fixup
            while (gi < 65 && c >  ugrid(gi))     ++gi;
            gq[q] = gi;
        }
#pragma unroll
        for (int q = 0; q < 4; q++) {
            int k = 4 * lane + q;
            for (int i = gq[q]; i < gq[q + 1]; ++i) s_ind[w][i] = k + 1;
        }
        if (lane == 31) {
            for (int i = gq[4]; i < 65; ++i) s_ind[w][i] = 129;
        }
    }
    __syncwarp();

    // ---- Stage B2: inverse-CDF interpolation --------------------------------
    for (int i = lane; i < T1 + 1; i += 32) {
        int idx = s_ind[w][i];
        int below = idx - 1;
        int above = idx > T0 ? T0 : idx;
        float u = ugrid(i);
        float c0 = fminf((s_cw[w][below] + 0.01f * (float)below) * invT, 1.0f);
        float c1 = fminf((s_cw[w][above] + 0.01f * (float)above) * invT, 1.0f);
        float t = __fdividef(u - c0, c1 - c0);
        if (isnan(t)) t = 0.0f;
        t = fminf(fmaxf(t, 0.0f), 1.0f);
        float b1v = ((float)below + t * (float)(above - below)) * (1.0f / 128.0f);
        s_b1[w][i] = b1v;
        s_rb1[w][i] = spacing_inv(sn * (1.0f - b1v) + sf * b1v);
    }
    __syncwarp();

    // ---- Stage C: fine weights1, weights_sum / depth / f_xyz ----------------
    const int i0 = 2 * lane, i1 = i0 + 1;
    float r0 = s_rb1[w][i0], r1 = s_rb1[w][i1], r2 = s_rb1[w][i1 + 1];
    float dsa = (r1 - r0) * sgf.x;
    float dsb = (r2 - r1) * sgf.y;
    float lca = dsa, lcb = lca + dsb;
    float scc = wscan_incl(lcb, lane);
    float bc = scc - lcb;
    float Ea = __expf(-bc);
    float Eb = __expf(-(bc + lca));
    float Ec = __expf(-(bc + lcb));
    float w1a = fmaxf(Ea - Eb, 0.0f);
    float w1b = fmaxf(Eb - Ec, 0.0f);
    s_w1[w][i0] = w1a;
    s_w1[w][i1] = w1b;
    float ta = 0.5f * (r0 + r1), tb = 0.5f * (r1 + r2);

    float ws  = w1a + w1b;
    float dep = w1a * ta + w1b * tb;
    float fx, fy, fz;
    {
        float cxa, cya, cza, cxb, cyb, czb;
        contract3(ox + dx * ta, oy + dy * ta, oz + dz * ta, cxa, cya, cza);
        contract3(ox + dx * tb, oy + dy * tb, oz + dz * tb, cxb, cyb, czb);
        fx = w1a * cxa + w1b * cxb;
        fy = w1a * cya + w1b * cyb;
        fz = w1a * cza + w1b * czb;
    }
    ws  = wreduce(ws);
    dep = wreduce(dep);
    fx  = wreduce(fx);
    fy  = wreduce(fy);
    fz  = wreduce(fz);
    if (lane == 0) {
        out[3 * N_RAYS + ray] = dep;
        out[4 * N_RAYS + ray * 3 + 0] = fx;
        out[4 * N_RAYS + ray * 3 + 1] = fy;
        out[4 * N_RAYS + ray * 3 + 2] = fz;
    }

    // ---- Stage E: interlevel (proposal) loss --------------------------------
    float prop;
    {
        float bA0 = s_b1[w][i0], bA1 = s_b1[w][i1], bA2 = s_b1[w][i1 + 1];
        int ilo = (int)floorf(bA0 * 128.0f); ilo = ilo < 0 ? 0 : (ilo > 127 ? 127 : ilo);
        int ihi = (int)floorf(bA1 * 128.0f); ihi = ihi < 0 ? 0 : (ihi > 127 ? 127 : ihi);
        float wseg = s_cw[w][ihi + 1] - s_cw[w][ilo];
        float dlt = fmaxf(w1a - wseg, 0.0f);
        prop = dlt * dlt * frcp(w1a + 1e-8f);
        ilo = (int)floorf(bA1 * 128.0f); ilo = ilo < 0 ? 0 : (ilo > 127 ? 127 : ilo);
        ihi = (int)floorf(bA2 * 128.0f); ihi = ihi < 0 ? 0 : (ihi > 127 ? 127 : ihi);
        wseg = s_cw[w][ihi + 1] - s_cw[w][ilo];
        dlt = fmaxf(w1b - wseg, 0.0f);
        prop += dlt * dlt * frcp(w1b + 1e-8f);
    }

    // ---- Stage F: efficient distortion loss ---------------------------------
    float uni, bi;
    {
        float bA0 = s_b1[w][i0], bA1 = s_b1[w][i1], bA2 = s_b1[w][i1 + 1];
        float inta = bA1 - bA0, intb = bA2 - bA1;
        float mida = bA0 + inta * 0.5f, midb = bA1 + intb * 0.5f;
        uni = inta * w1a * w1a + intb * w1b * w1b;
        float wma = w1a * mida, wmb = w1b * midb;
        float lw = w1a + w1b;
        float lm = wma + wmb;
        float siW = wscan_incl(lw, lane);
        float siM = wscan_incl(lm, lane);
        float exW_a = siW - lw, exW_b = exW_a + w1a;
        float exM_a = siM - lm, exM_b = exM_a + wma;
        bi = wma * exW_a - w1a * exM_a + wmb * exW_b - w1b * exM_b;
    }
    prop = wreduce(prop);
    uni  = wreduce(uni);
    bi   = wreduce(bi);
    if (lane == 0) {
        s_loss[0][w] = prop;
        s_loss[1][w] = uni;
        s_loss[2][w] = bi;
    }

    // ---- Stage D: colors weighted reduction (from prefetched smem) ----------
    {
        asm volatile("cp.async.wait_group 0;\n");
        __syncwarp();
        float4 acc = make_float4(0.f, 0.f, 0.f, 0.f);
#pragma unroll
        for (int it = 0; it < 8; ++it) {
            int f = it * 32 + lane;
            float4 cv = s_col[w][f];
            float wv = s_w1[w][f >> 2];
            acc.x += wv * cv.x; acc.y += wv * cv.y;
            acc.z += wv * cv.z; acc.w += wv * cv.w;
        }
#pragma unroll
        for (int o = 4; o < 32; o <<= 1) {
            acc.x += __shfl_xor_sync(FULLMASK, acc.x, o);
            acc.y += __shfl_xor_sync(FULLMASK, acc.y, o);
            acc.z += __shfl_xor_sync(FULLMASK, acc.z, o);
            acc.w += __shfl_xor_sync(FULLMASK, acc.w, o);
        }
        int g = lane & 3;
        float d0 = 0.f, d1 = 0.f, d2 = 0.f;
        float av[4] = {acc.x, acc.y, acc.z, acc.w};
#pragma unroll
        for (int j = 0; j < 4; j++) {
            int c = 4 * g + j;
            d0 += av[j] * w_view[c * 3 + 0];
            d1 += av[j] * w_view[c * 3 + 1];
            d2 += av[j] * w_view[c * 3 + 2];
        }
#pragma unroll
        for (int o = 1; o < 4; o <<= 1) {
            d0 += __shfl_xor_sync(FULLMASK, d0, o);
            d1 += __shfl_xor_sync(FULLMASK, d1, o);
            d2 += __shfl_xor_sync(FULLMASK, d2, o);
        }
        if (lane < 3) {
            float dv = (lane == 0) ? d0 : ((lane == 1) ? d1 : d2);
            float im = frcp(1.0f + __expf(-(dv + b_view[lane]))) + (1.0f - ws);
            out[ray * 3 + lane] = im;
        }
    }

    // ---- cross-block loss reduction: atomics + last-block finalize ----------
    __syncthreads();
    if (threadIdx.x == 0) {
        float p = 0.f, un = 0.f, bb = 0.f;
#pragma unroll
        for (int j = 0; j < WPB; j++) {
            p  += s_loss[0][j];
            un += s_loss[1][j];
            bb += s_loss[2][j];
        }
        atomicAdd(&g_acc[0], (double)p);
        atomicAdd(&g_acc[1], (double)un);
        atomicAdd(&g_acc[2], (double)bb);
        __threadfence();
        unsigned int t = atomicAdd(&g_cnt, 1u);
        if (t == (unsigned int)(NBLOCKS - 1)) {
            double rp = atomicAdd(&g_acc[0], 0.0);
            double ru = atomicAdd(&g_acc[1], 0.0);
            double rb = atomicAdd(&g_acc[2], 0.0);
            out[7 * N_RAYS]     = (float)(rp / ((double)N_RAYS * (double)T1));
            out[7 * N_RAYS + 1] = (float)(ru / (3.0 * (double)N_RAYS) +
                                          2.0 * rb / (double)N_RAYS);
            // reset for next (graph-replayed) launch
            g_acc[0] = 0.0; g_acc[1] = 0.0; g_acc[2] = 0.0;
            g_cnt = 0u;
        }
    }
}

extern "C" void kernel_launch(void* const* d_in, const int* in_sizes, int n_in,
                              void* d_out, int out_size) {
    const float* rays_o = (const float*)d_in[0];
    const float* rays_d = (const float*)d_in[1];
    const float* aabb   = (const float*)d_in[2];
    const float* sig_c  = (const float*)d_in[3];
    const float* sig_f  = (const float*)d_in[4];
    const float* colors = (const float*)d_in[5];
    const float* w_view = (const float*)d_in[6];
    const float* b_view = (const float*)d_in[7];
    float* out = (float*)d_out;

    nerf_render_kernel<<<NBLOCKS, WPB * 32>>>(
        rays_o, rays_d, aabb, sig_c, sig_f, colors, w_view, b_view, out);
}

// round 6
// speedup vs baseline: 1.7194x; 1.0274x over previous
#include <cuda_runtime.h>
#include <math.h>
#include <stdint.h>

#define N_RAYS 65536
#define T0 128
#define T1 64
#define WPB 8
#define NBLOCKS (N_RAYS / WPB)   // 8192
#define FULLMASK 0xffffffffu

// cross-block loss accumulators; zero at load, reset by last block each launch
__device__ double g_acc[3];
__device__ unsigned int g_cnt;

__device__ __forceinline__ float frcp(float x) { return __fdividef(1.0f, x); }
__device__ __forceinline__ float spacing_fn(float x) {
    return x < 1.0f ? 0.5f * x : 1.0f - 0.5f * frcp(x);
}
__device__ __forceinline__ float spacing_inv(float x) {
    return x < 0.5f ? 2.0f * x : frcp(2.0f - 2.0f * x);
}
__device__ __forceinline__ float wscan_incl(float x, int lane) {
#pragma unroll
    for (int o = 1; o < 32; o <<= 1) {
        float v = __shfl_up_sync(FULLMASK, x, o);
        if (lane >= o) x += v;
    }
    return x;
}
__device__ __forceinline__ float wreduce(float x) {
#pragma unroll
    for (int o = 16; o; o >>= 1) x += __shfl_xor_sync(FULLMASK, x, o);
    return x;
}
// MERF contraction matching jnp reference
__device__ __forceinline__ void contract3(float x, float y, float z,
                                          float& cx, float& cy, float& cz) {
    float ax = fabsf(x), ay = fabsf(y), az = fabsf(z);
    float mag = fmaxf(ax, fmaxf(ay, az));
    int idx = (ax >= ay && ax >= az) ? 0 : ((ay >= az) ? 1 : 2);
    float inv = frcp(mag);
    float ss = (2.0f - inv) * inv;
    float sx = (idx == 0) ? ss : inv;
    float sy = (idx == 1) ? ss : inv;
    float sz = (idx == 2) ? ss : inv;
    if (mag < 1.0f) { cx = x; cy = y; cz = z; }
    else            { cx = x * sx; cy = y * sy; cz = z * sz; }
}
__device__ __forceinline__ float ugrid(int i) {
    return ((float)i + 0.5f) * (1.0f / 65.0f);
}

__global__ __launch_bounds__(WPB * 32, 4)
void nerf_render_kernel(const float* __restrict__ rays_o,
                        const float* __restrict__ rays_d,
                        const float* __restrict__ aabb,
                        const float* __restrict__ sig_c,
                        const float* __restrict__ sig_f,
                        const float* __restrict__ colors,
                        const float* __restrict__ w_view,
                        const float* __restrict__ b_view,
                        float* __restrict__ out) {
    __shared__ float  s_cw [WPB][T0 + 1];
    __shared__ int    s_ind[WPB][T1 + 1];
    __shared__ float  s_b1 [WPB][T1 + 1];
    __shared__ float  s_rb1[WPB][T1 + 1];
    __shared__ float  s_w1 [WPB][T1];
    __shared__ float4 s_col[WPB][T1 * 4];
    __shared__ float  s_loss[3][WPB];

    const int lane = threadIdx.x & 31;
    const int w    = threadIdx.x >> 5;
    const int ray  = blockIdx.x * WPB + w;

    // ---- prefetch colors (256 float4 per ray) into shared via cp.async ------
    {
        const float4* c4 = (const float4*)colors + (size_t)ray * 256;
        uint32_t sbase = (uint32_t)__cvta_generic_to_shared(&s_col[w][0]);
#pragma unroll
        for (int it = 0; it < 8; ++it) {
            int f = it * 32 + lane;
            asm volatile("cp.async.cg.shared.global [%0], [%1], 16;\n"
                         :: "r"(sbase + f * 16), "l"(c4 + f));
        }
        asm volatile("cp.async.commit_group;\n");
    }
    const float4 sg  = *(const float4*)(sig_c + (size_t)ray * T0 + 4 * lane);
    const float2 sgf = *(const float2*)(sig_f + (size_t)ray * T1 + 2 * lane);

    const float ox = rays_o[ray * 3 + 0], oy = rays_o[ray * 3 + 1], oz = rays_o[ray * 3 + 2];
    const float dx = rays_d[ray * 3 + 0], dy = rays_d[ray * 3 + 1], dz = rays_d[ray * 3 + 2];

    float rx = frcp(dx + 1e-15f), ry = frcp(dy + 1e-15f), rz = frcp(dz + 1e-15f);
    float t0x = (aabb[0] - ox) * rx, t1x = (aabb[3] - ox) * rx;
    float t0y = (aabb[1] - oy) * ry, t1y = (aabb[4] - oy) * ry;
    float t0z = (aabb[2] - oz) * rz, t1z = (aabb[5] - oz) * rz;
    float nearv = fmaxf(fmaxf(fminf(t0x, t1x), fminf(t0y, t1y)), fminf(t0z, t1z));
    float farv  = fminf(fminf(fmaxf(t0x, t1x), fmaxf(t0y, t1y)), fmaxf(t0z, t1z));
    bool bad = farv < nearv;
    nearv = fmaxf(bad ? 1e9f : nearv, 0.05f);
    farv  = bad ? 1e9f : farv;
    const float sn = spacing_fn(nearv), sf = spacing_fn(farv);

    // ---- Stage A: coarse transmittance; cw[k] = 1 - E_k (telescoped) --------
    float e[5];
#pragma unroll
    for (int q = 0; q < 5; q++) {
        float b = (float)(4 * lane + q) * (1.0f / 128.0f);
        e[q] = spacing_inv(sn * (1.0f - b) + sf * b);
    }
    float ds0 = (e[1] - e[0]) * sg.x;
    float ds1 = (e[2] - e[1]) * sg.y;
    float ds2 = (e[3] - e[2]) * sg.z;
    float ds3 = (e[4] - e[3]) * sg.w;
    float la0 = ds0, la1 = la0 + ds1, la2 = la1 + ds2, la3 = la2 + ds3;
    float scn = wscan_incl(la3, lane);
    float baseA = scn - la3;                 // cum ds at k = 4*lane
    float E1 = __expf(-(baseA + la0));
    float E2 = __expf(-(baseA + la1));
    float E3 = __expf(-(baseA + la2));
    float E4 = __expf(-(baseA + la3));
    float cw1v = 1.0f - E1, cw2v = 1.0f - E2, cw3v = 1.0f - E3, cw4v = 1.0f - E4;
    if (lane == 0) s_cw[w][0] = 0.0f;
    s_cw[w][4 * lane + 1] = cw1v;
    s_cw[w][4 * lane + 2] = cw2v;
    s_cw[w][4 * lane + 3] = cw3v;
    s_cw[w][4 * lane + 4] = cw4v;
    float invT;
    {
        float Elast = __shfl_sync(FULLMASK, E4, 31);
        invT = frcp((1.0f - Elast) + 0.01f * 128.0f);
    }

    // ---- Stage B1: scatter sample->bin index table (register-only) ----------
    // cdf(k) = min((cw[k] + 0.01k) * invT, 1), strictly increasing.
    // Lane boundary uses shfl_up of the SAME register bits lane-1 stored to
    // s_cw, so adjacent lanes agree bitwise: gap-free, write-once fill.
    {
        float cw0v = __shfl_up_sync(FULLMASK, cw4v, 1);
        if (lane == 0) cw0v = 0.0f;
        float cw_l[5] = {cw0v, cw1v, cw2v, cw3v, cw4v};
        int gq[5];
#pragma unroll
        for (int q = 0; q < 5; q++) {
            int k = 4 * lane + q;
            float c = fminf((cw_l[q] + 0.01f * (float)k) * invT, 1.0f);
            int gi = (int)ceilf(c * 65.0f - 0.5f);
            gi = gi < 0 ? 0 : (gi > 65 ? 65 : gi);
            while (gi > 0  && c <= ugrid(gi - 1)) --gi;   // exact fixup
            while (gi < 65 && c >  ugrid(gi))     ++gi;
            gq[q] = gi;
        }
#pragma unroll
        for (int q = 0; q < 4; q++) {
            int k = 4 * lane + q;
            for (int i = gq[q]; i < gq[q + 1]; ++i) s_ind[w][i] = k + 1;
        }
        if (lane == 31) {
            for (int i = gq[4]; i < 65; ++i) s_ind[w][i] = 129;
        }
    }
    __syncwarp();   // s_cw + s_ind visible

    // ---- Stage B2: inverse-CDF interpolation (3 known trips) ----------------
    {
        auto interp = [&](int i) {
            int idx = s_ind[w][i];
            int below = idx - 1;
            int above = idx > T0 ? T0 : idx;
            float u = ugrid(i);
            float c0 = fminf((s_cw[w][below] + 0.01f * (float)below) * invT, 1.0f);
            float c1 = fminf((s_cw[w][above] + 0.01f * (float)above) * invT, 1.0f);
            float t = __fdividef(u - c0, c1 - c0);
            if (isnan(t)) t = 0.0f;
            t = fminf(fmaxf(t, 0.0f), 1.0f);
            float b1v = ((float)below + t * (float)(above - below)) * (1.0f / 128.0f);
            s_b1[w][i] = b1v;
            s_rb1[w][i] = spacing_inv(sn * (1.0f - b1v) + sf * b1v);
        };
        interp(lane);
        interp(lane + 32);
        if (lane == 0) interp(64);
    }
    __syncwarp();

    // ---- Stage C: fine weights1; ws telescoped ------------------------------
    const int i0 = 2 * lane, i1 = i0 + 1;
    float r0 = s_rb1[w][i0], r1 = s_rb1[w][i1], r2 = s_rb1[w][i1 + 1];
    float dsa = (r1 - r0) * sgf.x;
    float dsb = (r2 - r1) * sgf.y;
    float lca = dsa, lcb = lca + dsb;
    float scc = wscan_incl(lcb, lane);
    float bc = scc - lcb;
    float Ea = __expf(-bc);
    float Eb = __expf(-(bc + lca));
    float Ec = __expf(-(bc + lcb));
    float w1a = fmaxf(Ea - Eb, 0.0f);
    float w1b = fmaxf(Eb - Ec, 0.0f);
    s_w1[w][i0] = w1a;
    s_w1[w][i1] = w1b;
    float ta = 0.5f * (r0 + r1), tb = 0.5f * (r1 + r2);

    float ws = 1.0f - __shfl_sync(FULLMASK, Ec, 31);   // sum(w1) telescoped
    float dep = w1a * ta + w1b * tb;
    float fx, fy, fz;
    {
        float cxa, cya, cza, cxb, cyb, czb;
        contract3(ox + dx * ta, oy + dy * ta, oz + dz * ta, cxa, cya, cza);
        contract3(ox + dx * tb, oy + dy * tb, oz + dz * tb, cxb, cyb, czb);
        fx = w1a * cxa + w1b * cxb;
        fy = w1a * cya + w1b * cyb;
        fz = w1a * cza + w1b * czb;
    }
    dep = wreduce(dep);
    fx  = wreduce(fx);
    fy  = wreduce(fy);
    fz  = wreduce(fz);
    if (lane == 0) {
        out[3 * N_RAYS + ray] = dep;
        out[4 * N_RAYS + ray * 3 + 0] = fx;
        out[4 * N_RAYS + ray * 3 + 1] = fy;
        out[4 * N_RAYS + ray * 3 + 2] = fz;
    }

    // ---- Stage E: interlevel (proposal) loss --------------------------------
    float prop;
    {
        float bA0 = s_b1[w][i0], bA1 = s_b1[w][i1], bA2 = s_b1[w][i1 + 1];
        int ilo = (int)floorf(bA0 * 128.0f); ilo = ilo < 0 ? 0 : (ilo > 127 ? 127 : ilo);
        int ihi = (int)floorf(bA1 * 128.0f); ihi = ihi < 0 ? 0 : (ihi > 127 ? 127 : ihi);
        float wseg = s_cw[w][ihi + 1] - s_cw[w][ilo];
        float dlt = fmaxf(w1a - wseg, 0.0f);
        prop = dlt * dlt * frcp(w1a + 1e-8f);
        ilo = (int)floorf(bA1 * 128.0f); ilo = ilo < 0 ? 0 : (ilo > 127 ? 127 : ilo);
        ihi = (int)floorf(bA2 * 128.0f); ihi = ihi < 0 ? 0 : (ihi > 127 ? 127 : ihi);
        wseg = s_cw[w][ihi + 1] - s_cw[w][ilo];
        dlt = fmaxf(w1b - wseg, 0.0f);
        prop += dlt * dlt * frcp(w1b + 1e-8f);
    }

    // ---- Stage F: distortion loss; exW telescoped (1 - Ea/Eb) ---------------
    float uni, bi;
    {
        float bA0 = s_b1[w][i0], bA1 = s_b1[w][i1], bA2 = s_b1[w][i1 + 1];
        float inta = bA1 - bA0, intb = bA2 - bA1;
        float mida = bA0 + inta * 0.5f, midb = bA1 + intb * 0.5f;
        uni = inta * w1a * w1a + intb * w1b * w1b;
        float wma = w1a * mida, wmb = w1b * midb;
        float exW_a = 1.0f - Ea, exW_b = 1.0f - Eb;   // cumsum(w1) telescoped
        float lm = wma + wmb;
        float siM = wscan_incl(lm, lane);
        float exM_a = siM - lm, exM_b = exM_a + wma;
        bi = wma * exW_a - w1a * exM_a + wmb * exW_b - w1b * exM_b;
    }
    prop = wreduce(prop);
    uni  = wreduce(uni);
    bi   = wreduce(bi);
    if (lane == 0) {
        s_loss[0][w] = prop;
        s_loss[1][w] = uni;
        s_loss[2][w] = bi;
    }

    // ---- Stage D: colors reduction; matmul before cross-lane reduce ---------
    {
        asm volatile("cp.async.wait_group 0;\n");
        __syncwarp();
        float4 acc = make_float4(0.f, 0.f, 0.f, 0.f);
#pragma unroll
        for (int it = 0; it < 8; ++it) {
            int f = it * 32 + lane;
            float4 cv = s_col[w][f];
            float wv = s_w1[w][f >> 2];
            acc.x += wv * cv.x; acc.y += wv * cv.y;
            acc.z += wv * cv.z; acc.w += wv * cv.w;
        }
        // fold through w_view first (channel group g = lane&3), then one
        // 5-level butterfly over 3 scalars
        int g = lane & 3;
        float av[4] = {acc.x, acc.y, acc.z, acc.w};
        float d0 = 0.f, d1 = 0.f, d2 = 0.f;
#pragma unroll
        for (int j = 0; j < 4; j++) {
            int c = 4 * g + j;
            d0 += av[j] * w_view[c * 3 + 0];
            d1 += av[j] * w_view[c * 3 + 1];
            d2 += av[j] * w_view[c * 3 + 2];
        }
        d0 = wreduce(d0);
        d1 = wreduce(d1);
        d2 = wreduce(d2);
        if (lane < 3) {
            float dv = (lane == 0) ? d0 : ((lane == 1) ? d1 : d2);
            float im = frcp(1.0f + __expf(-(dv + b_view[lane]))) + (1.0f - ws);
            out[ray * 3 + lane] = im;
        }
    }

    // ---- cross-block loss reduction: atomics + last-block finalize ----------
    __syncthreads();
    if (threadIdx.x == 0) {
        float p = 0.f, un = 0.f, bb = 0.f;
#pragma unroll
        for (int j = 0; j < WPB; j++) {
            p  += s_loss[0][j];
            un += s_loss[1][j];
            bb += s_loss[2][j];
        }
        atomicAdd(&g_acc[0], (double)p);
        atomicAdd(&g_acc[1], (double)un);
        atomicAdd(&g_acc[2], (double)bb);
        __threadfence();
        unsigned int t = atomicAdd(&g_cnt, 1u);
        if (t == (unsigned int)(NBLOCKS - 1)) {
            double rp = atomicAdd(&g_acc[0], 0.0);
            double ru = atomicAdd(&g_acc[1], 0.0);
            double rb = atomicAdd(&g_acc[2], 0.0);
            out[7 * N_RAYS]     = (float)(rp / ((double)N_RAYS * (double)T1));
            out[7 * N_RAYS + 1] = (float)(ru / (3.0 * (double)N_RAYS) +
                                          2.0 * rb / (double)N_RAYS);
            g_acc[0] = 0.0; g_acc[1] = 0.0; g_acc[2] = 0.0;
            g_cnt = 0u;
        }
    }
}

extern "C" void kernel_launch(void* const* d_in, const int* in_sizes, int n_in,
                              void* d_out, int out_size) {
    const float* rays_o = (const float*)d_in[0];
    const float* rays_d = (const float*)d_in[1];
    const float* aabb   = (const float*)d_in[2];
    const float* sig_c  = (const float*)d_in[3];
    const float* sig_f  = (const float*)d_in[4];
    const float* colors = (const float*)d_in[5];
    const float* w_view = (const float*)d_in[6];
    const float* b_view = (const float*)d_in[7];
    float* out = (float*)d_out;

    nerf_render_kernel<<<NBLOCKS, WPB * 32>>>(
        rays_o, rays_d, aabb, sig_c, sig_f, colors, w_view, b_view, out);
}

// round 9
// speedup vs baseline: 1.9246x; 1.1194x over previous
#include <cuda_runtime.h>
#include <math.h>
#include <stdint.h>

#define N_RAYS 65536
#define T0 128
#define T1 64
#define WPB 8
#define NBLOCKS (N_RAYS / WPB)   // 8192
#define FULLMASK 0xffffffffu

// cross-block loss accumulators; zero at load, reset by last block each launch
__device__ double g_acc[3];
__device__ unsigned int g_cnt;

__device__ __forceinline__ float frcp(float x) { return __fdividef(1.0f, x); }
__device__ __forceinline__ float spacing_fn(float x) {
    return x < 1.0f ? 0.5f * x : 1.0f - 0.5f * frcp(x);
}
__device__ __forceinline__ float spacing_inv(float x) {
    return x < 0.5f ? 2.0f * x : frcp(2.0f - 2.0f * x);
}
__device__ __forceinline__ float wscan_incl(float x, int lane) {
#pragma unroll
    for (int o = 1; o < 32; o <<= 1) {
        float v = __shfl_up_sync(FULLMASK, x, o);
        if (lane >= o) x += v;
    }
    return x;
}
__device__ __forceinline__ float wreduce(float x) {
#pragma unroll
    for (int o = 16; o; o >>= 1) x += __shfl_xor_sync(FULLMASK, x, o);
    return x;
}
// MERF contraction matching jnp reference
__device__ __forceinline__ void contract3(float x, float y, float z,
                                          float& cx, float& cy, float& cz) {
    float ax = fabsf(x), ay = fabsf(y), az = fabsf(z);
    float mag = fmaxf(ax, fmaxf(ay, az));
    int idx = (ax >= ay && ax >= az) ? 0 : ((ay >= az) ? 1 : 2);
    float inv = frcp(mag);
    float ss = (2.0f - inv) * inv;
    float sx = (idx == 0) ? ss : inv;
    float sy = (idx == 1) ? ss : inv;
    float sz = (idx == 2) ? ss : inv;
    if (mag < 1.0f) { cx = x; cy = y; cz = z; }
    else            { cx = x * sx; cy = y * sy; cz = z * sz; }
}
__device__ __forceinline__ float ugrid(int i) {
    return ((float)i + 0.5f) * (1.0f / 65.0f);
}
// packed f32x2 fma: d = a*b + d  (both halves)
__device__ __forceinline__ void ffma2(unsigned long long& d,
                                      unsigned long long a,
                                      unsigned long long b) {
    asm("fma.rn.f32x2 %0, %1, %2, %0;" : "+l"(d) : "l"(a), "l"(b));
}

__global__ __launch_bounds__(WPB * 32, 5)
void nerf_render_kernel(const float* __restrict__ rays_o,
                        const float* __restrict__ rays_d,
                        const float* __restrict__ aabb,
                        const float* __restrict__ sig_c,
                        const float* __restrict__ sig_f,
                        const float* __restrict__ colors,
                        const float* __restrict__ w_view,
                        const float* __restrict__ b_view,
                        float* __restrict__ out) {
    __shared__ float   s_cw [WPB][T0 + 1];
    __shared__ uint8_t s_ind[WPB][T1 + 4];
    __shared__ float   s_b1 [WPB][T1 + 1];
    __shared__ float   s_rb1[WPB][T1 + 1];
    __shared__ float4  s_col[WPB][T1 * 4];
    __shared__ float   s_loss[3][WPB];

    const int lane = threadIdx.x & 31;
    const int w    = threadIdx.x >> 5;
    const int ray  = blockIdx.x * WPB + w;

    // ---- prefetch colors (256 float4 per ray) into shared via cp.async ------
    {
        const float4* c4 = (const float4*)colors + (size_t)ray * 256;
        uint32_t sbase = (uint32_t)__cvta_generic_to_shared(&s_col[w][0]);
#pragma unroll
        for (int it = 0; it < 8; ++it) {
            int f = it * 32 + lane;
            asm volatile("cp.async.cg.shared.global [%0], [%1], 16;\n"
                         :: "r"(sbase + f * 16), "l"(c4 + f));
        }
        asm volatile("cp.async.commit_group;\n");
    }
    const float4 sg  = *(const float4*)(sig_c + (size_t)ray * T0 + 4 * lane);
    const float2 sgf = *(const float2*)(sig_f + (size_t)ray * T1 + 2 * lane);

    const float ox = rays_o[ray * 3 + 0], oy = rays_o[ray * 3 + 1], oz = rays_o[ray * 3 + 2];
    const float dx = rays_d[ray * 3 + 0], dy = rays_d[ray * 3 + 1], dz = rays_d[ray * 3 + 2];

    float rx = frcp(dx + 1e-15f), ry = frcp(dy + 1e-15f), rz = frcp(dz + 1e-15f);
    float t0x = (aabb[0] - ox) * rx, t1x = (aabb[3] - ox) * rx;
    float t0y = (aabb[1] - oy) * ry, t1y = (aabb[4] - oy) * ry;
    float t0z = (aabb[2] - oz) * rz, t1z = (aabb[5] - oz) * rz;
    float nearv = fmaxf(fmaxf(fminf(t0x, t1x), fminf(t0y, t1y)), fminf(t0z, t1z));
    float farv  = fminf(fminf(fmaxf(t0x, t1x), fmaxf(t0y, t1y)), fmaxf(t0z, t1z));
    bool bad = farv < nearv;
    nearv = fmaxf(bad ? 1e9f : nearv, 0.05f);
    farv  = bad ? 1e9f : farv;
    const float sn = spacing_fn(nearv), sf = spacing_fn(farv);

    // ---- Stage A: coarse transmittance; cw[k] = 1 - E_k (telescoped) --------
    float e[5];
#pragma unroll
    for (int q = 0; q < 5; q++) {
        float b = (float)(4 * lane + q) * (1.0f / 128.0f);
        e[q] = spacing_inv(sn * (1.0f - b) + sf * b);
    }
    float ds0 = (e[1] - e[0]) * sg.x;
    float ds1 = (e[2] - e[1]) * sg.y;
    float ds2 = (e[3] - e[2]) * sg.z;
    float ds3 = (e[4] - e[3]) * sg.w;
    float la0 = ds0, la1 = la0 + ds1, la2 = la1 + ds2, la3 = la2 + ds3;
    float scn = wscan_incl(la3, lane);
    float baseA = scn - la3;                 // cum ds at k = 4*lane
    float E1 = __expf(-(baseA + la0));
    float E2 = __expf(-(baseA + la1));
    float E3 = __expf(-(baseA + la2));
    float E4 = __expf(-(baseA + la3));
    float cw1v = 1.0f - E1, cw2v = 1.0f - E2, cw3v = 1.0f - E3, cw4v = 1.0f - E4;
    if (lane == 0) s_cw[w][0] = 0.0f;
    s_cw[w][4 * lane + 1] = cw1v;
    s_cw[w][4 * lane + 2] = cw2v;
    s_cw[w][4 * lane + 3] = cw3v;
    s_cw[w][4 * lane + 4] = cw4v;
    float invT;
    {
        float Elast = __shfl_sync(FULLMASK, E4, 31);
        invT = frcp((1.0f - Elast) + 0.01f * 128.0f);
    }

    // ---- Stage B1: scatter sample->bin index table (register-only) ----------
    // cdf(k) = min((cw[k] + 0.01k) * invT, 1), strictly increasing; lane
    // boundary via shfl_up of the same register bits -> bitwise-consistent,
    // gap-free write-once fill.
    {
        float cw0v = __shfl_up_sync(FULLMASK, cw4v, 1);
        if (lane == 0) cw0v = 0.0f;
        float cw_l[5] = {cw0v, cw1v, cw2v, cw3v, cw4v};
        int gq[5];
#pragma unroll
        for (int q = 0; q < 5; q++) {
            int k = 4 * lane + q;
            float c = fminf((cw_l[q] + 0.01f * (float)k) * invT, 1.0f);
            int gi = (int)ceilf(c * 65.0f - 0.5f);
            gi = gi < 0 ? 0 : (gi > 65 ? 65 : gi);
            while (gi > 0  && c <= ugrid(gi - 1)) --gi;   // exact fixup
            while (gi < 65 && c >  ugrid(gi))     ++gi;
            gq[q] = gi;
        }
#pragma unroll
        for (int q = 0; q < 4; q++) {
            int k = 4 * lane + q;
            for (int i = gq[q]; i < gq[q + 1]; ++i) s_ind[w][i] = (uint8_t)(k + 1);
        }
        if (lane == 31) {
            for (int i = gq[4]; i < 65; ++i) s_ind[w][i] = 129;
        }
    }
    __syncwarp();   // s_cw + s_ind visible

    // ---- Stage B2: inverse-CDF interpolation (3 known trips) ----------------
    {
        auto interp = [&](int i) {
            int idx = (int)s_ind[w][i];
            int below = idx - 1;
            int above = idx > T0 ? T0 : idx;
            float u = ugrid(i);
            float c0 = fminf((s_cw[w][below] + 0.01f * (float)below) * invT, 1.0f);
            float c1 = fminf((s_cw[w][above] + 0.01f * (float)above) * invT, 1.0f);
            float t = __fdividef(u - c0, c1 - c0);
            if (isnan(t)) t = 0.0f;
            t = fminf(fmaxf(t, 0.0f), 1.0f);
            float b1v = ((float)below + t * (float)(above - below)) * (1.0f / 128.0f);
            s_b1[w][i] = b1v;
            s_rb1[w][i] = spacing_inv(sn * (1.0f - b1v) + sf * b1v);
        };
        interp(lane);
        interp(lane + 32);
        if (lane == 0) interp(64);
    }
    __syncwarp();

    // ---- Stage C: fine weights1; ws telescoped ------------------------------
    const int i0 = 2 * lane, i1 = i0 + 1;
    float r0 = s_rb1[w][i0], r1 = s_rb1[w][i1], r2 = s_rb1[w][i1 + 1];
    float dsa = (r1 - r0) * sgf.x;
    float dsb = (r2 - r1) * sgf.y;
    float lca = dsa, lcb = lca + dsb;
    float scc = wscan_incl(lcb, lane);
    float bc = scc - lcb;
    float Ea = __expf(-bc);
    float Eb = __expf(-(bc + lca));
    float Ec = __expf(-(bc + lcb));
    float w1a = fmaxf(Ea - Eb, 0.0f);
    float w1b = fmaxf(Eb - Ec, 0.0f);
    float ta = 0.5f * (r0 + r1), tb = 0.5f * (r1 + r2);

    float ws = 1.0f - __shfl_sync(FULLMASK, Ec, 31);   // sum(w1) telescoped
    float dep = w1a * ta + w1b * tb;
    float fx, fy, fz;
    {
        float cxa, cya, cza, cxb, cyb, czb;
        contract3(ox + dx * ta, oy + dy * ta, oz + dz * ta, cxa, cya, cza);
        contract3(ox + dx * tb, oy + dy * tb, oz + dz * tb, cxb, cyb, czb);
        fx = w1a * cxa + w1b * cxb;
        fy = w1a * cya + w1b * cyb;
        fz = w1a * cza + w1b * czb;
    }
    dep = wreduce(dep);
    fx  = wreduce(fx);
    fy  = wreduce(fy);
    fz  = wreduce(fz);
    if (lane == 0) {
        out[3 * N_RAYS + ray] = dep;
        out[4 * N_RAYS + ray * 3 + 0] = fx;
        out[4 * N_RAYS + ray * 3 + 1] = fy;
        out[4 * N_RAYS + ray * 3 + 2] = fz;
    }

    // ---- Stage E: interlevel (proposal) loss --------------------------------
    float prop;
    {
        float bA0 = s_b1[w][i0], bA1 = s_b1[w][i1], bA2 = s_b1[w][i1 + 1];
        int ilo = (int)floorf(bA0 * 128.0f); ilo = ilo < 0 ? 0 : (ilo > 127 ? 127 : ilo);
        int ihi = (int)floorf(bA1 * 128.0f); ihi = ihi < 0 ? 0 : (ihi > 127 ? 127 : ihi);
        float wseg = s_cw[w][ihi + 1] - s_cw[w][ilo];
        float dlt = fmaxf(w1a - wseg, 0.0f);
        prop = dlt * dlt * frcp(w1a + 1e-8f);
        ilo = (int)floorf(bA1 * 128.0f); ilo = ilo < 0 ? 0 : (ilo > 127 ? 127 : ilo);
        ihi = (int)floorf(bA2 * 128.0f); ihi = ihi < 0 ? 0 : (ihi > 127 ? 127 : ihi);
        wseg = s_cw[w][ihi + 1] - s_cw[w][ilo];
        dlt = fmaxf(w1b - wseg, 0.0f);
        prop += dlt * dlt * frcp(w1b + 1e-8f);
    }

    // ---- Stage F: distortion loss; exW telescoped ---------------------------
    float uni, bi;
    {
        float bA0 = s_b1[w][i0], bA1 = s_b1[w][i1], bA2 = s_b1[w][i1 + 1];
        float inta = bA1 - bA0, intb = bA2 - bA1;
        float mida = bA0 + inta * 0.5f, midb = bA1 + intb * 0.5f;
        uni = inta * w1a * w1a + intb * w1b * w1b;
        float wma = w1a * mida, wmb = w1b * midb;
        float exW_a = 1.0f - Ea, exW_b = 1.0f - Eb;
        float lm = wma + wmb;
        float siM = wscan_incl(lm, lane);
        float exM_a = siM - lm, exM_b = exM_a + wma;
        bi = wma * exW_a - w1a * exM_a + wmb * exW_b - w1b * exM_b;
    }
    prop = wreduce(prop);
    uni  = wreduce(uni);
    bi   = wreduce(bi);
    if (lane == 0) {
        s_loss[0][w] = prop;
        s_loss[1][w] = uni;
        s_loss[2][w] = bi;
    }

    // ---- Stage D: colors reduction (weights via dual shfl, f32x2 FMA) -------
    {
        asm volatile("cp.async.wait_group 0;\n");
        __syncwarp();
        // weight for float4-index f = it*32+lane: w1[f>>2] with
        // f>>2 = it*8 + (lane>>2) = 2*src + ((lane>>2)&1), src = it*4+(lane>>3).
        // Shuffle BOTH halves from src, select with the DEST's parity bit.
        const int wsrc_base = lane >> 3;
        const bool use_b = (lane & 4) != 0;
        unsigned long long acc01 = 0ull, acc23 = 0ull;
#pragma unroll
        for (int it = 0; it < 8; ++it) {
            const unsigned long long* cp =
                (const unsigned long long*)&s_col[w][it * 32 + lane];
            unsigned long long c01 = cp[0], c23 = cp[1];
            int src = wsrc_base + it * 4;
            float wa = __shfl_sync(FULLMASK, w1a, src);
            float wb = __shfl_sync(FULLMASK, w1b, src);
            float wv = use_b ? wb : wa;
            unsigned long long wv2;
            asm("mov.b64 %0, {%1, %1};" : "=l"(wv2) : "r"(__float_as_uint(wv)));
            ffma2(acc01, c01, wv2);
            ffma2(acc23, c23, wv2);
        }
        float a0 = __uint_as_float((unsigned)(acc01 & 0xffffffffull));
        float a1 = __uint_as_float((unsigned)(acc01 >> 32));
        float a2 = __uint_as_float((unsigned)(acc23 & 0xffffffffull));
        float a3 = __uint_as_float((unsigned)(acc23 >> 32));
        // fold through w_view (channel group g = lane&3), then butterfly
        int g = lane & 3;
        float av[4] = {a0, a1, a2, a3};
        float d0 = 0.f, d1 = 0.f, d2 = 0.f;
#pragma unroll
        for (int j = 0; j < 4; j++) {
            int c = 4 * g + j;
            d0 += av[j] * w_view[c * 3 + 0];
            d1 += av[j] * w_view[c * 3 + 1];
            d2 += av[j] * w_view[c * 3 + 2];
        }
        d0 = wreduce(d0);
        d1 = wreduce(d1);
        d2 = wreduce(d2);
        if (lane < 3) {
            float dv = (lane == 0) ? d0 : ((lane == 1) ? d1 : d2);
            float im = frcp(1.0f + __expf(-(dv + b_view[lane]))) + (1.0f - ws);
            out[ray * 3 + lane] = im;
        }
    }

    // ---- cross-block loss reduction: atomics + last-block finalize ----------
    __syncthreads();
    if (threadIdx.x == 0) {
        float p = 0.f, un = 0.f, bb = 0.f;
#pragma unroll
        for (int j = 0; j < WPB; j++) {
            p  += s_loss[0][j];
            un += s_loss[1][j];
            bb += s_loss[2][j];
        }
        atomicAdd(&g_acc[0], (double)p);
        atomicAdd(&g_acc[1], (double)un);
        atomicAdd(&g_acc[2], (double)bb);
        __threadfence();
        unsigned int t = atomicAdd(&g_cnt, 1u);
        if (t == (unsigned int)(NBLOCKS - 1)) {
            double rp = atomicAdd(&g_acc[0], 0.0);
            double ru = atomicAdd(&g_acc[1], 0.0);
            double rb = atomicAdd(&g_acc[2], 0.0);
            out[7 * N_RAYS]     = (float)(rp / ((double)N_RAYS * (double)T1));
            out[7 * N_RAYS + 1] = (float)(ru / (3.0 * (double)N_RAYS) +
                                          2.0 * rb / (double)N_RAYS);
            g_acc[0] = 0.0; g_acc[1] = 0.0; g_acc[2] = 0.0;
            g_cnt = 0u;
        }
    }
}

extern "C" void kernel_launch(void* const* d_in, const int* in_sizes, int n_in,
                              void* d_out, int out_size) {
    const float* rays_o = (const float*)d_in[0];
    const float* rays_d = (const float*)d_in[1];
    const float* aabb   = (const float*)d_in[2];
    const float* sig_c  = (const float*)d_in[3];
    const float* sig_f  = (const float*)d_in[4];
    const float* colors = (const float*)d_in[5];
    const float* w_view = (const float*)d_in[6];
    const float* b_view = (const float*)d_in[7];
    float* out = (float*)d_out;

    nerf_render_kernel<<<NBLOCKS, WPB * 32>>>(
        rays_o, rays_d, aabb, sig_c, sig_f, colors, w_view, b_view, out);
}

// round 10
// speedup vs baseline: 1.9349x; 1.0053x over previous
#include <cuda_runtime.h>
#include <math.h>
#include <stdint.h>

#define N_RAYS 65536
#define T0 128
#define T1 64
#define WPB 8
#define NBLOCKS (N_RAYS / WPB)   // 8192
#define FULLMASK 0xffffffffu

// cross-block loss accumulators; zero at load, reset by last block each launch
__device__ double g_acc[3];
__device__ unsigned int g_cnt;

__device__ __forceinline__ float frcp(float x) { return __fdividef(1.0f, x); }
__device__ __forceinline__ float spacing_fn(float x) {
    return x < 1.0f ? 0.5f * x : 1.0f - 0.5f * frcp(x);
}
__device__ __forceinline__ float spacing_inv(float x) {
    return x < 0.5f ? 2.0f * x : frcp(2.0f - 2.0f * x);
}
__device__ __forceinline__ float wscan_incl(float x, int lane) {
#pragma unroll
    for (int o = 1; o < 32; o <<= 1) {
        float v = __shfl_up_sync(FULLMASK, x, o);
        if (lane >= o) x += v;
    }
    return x;
}
__device__ __forceinline__ float wreduce(float x) {
#pragma unroll
    for (int o = 16; o; o >>= 1) x += __shfl_xor_sync(FULLMASK, x, o);
    return x;
}
// ---- packed f32x2 helpers (rounding identical to scalar FADD/FFMA) ---------
__device__ __forceinline__ unsigned long long pack2(float a, float b) {
    unsigned long long r;
    asm("mov.b64 %0, {%1, %2};" : "=l"(r) : "f"(a), "f"(b));
    return r;
}
__device__ __forceinline__ void unpack2(unsigned long long v, float& a, float& b) {
    asm("mov.b64 {%0, %1}, %2;" : "=f"(a), "=f"(b) : "l"(v));
}
__device__ __forceinline__ void ffma2(unsigned long long& d,
                                      unsigned long long a,
                                      unsigned long long b) {
    asm("fma.rn.f32x2 %0, %1, %2, %0;" : "+l"(d) : "l"(a), "l"(b));
}
__device__ __forceinline__ unsigned long long wreduce2(unsigned long long x) {
#pragma unroll
    for (int o = 16; o; o >>= 1) {
        unsigned long long y = __shfl_xor_sync(FULLMASK, x, o);
        asm("add.rn.f32x2 %0, %0, %1;" : "+l"(x) : "l"(y));
    }
    return x;
}
// MERF contraction matching jnp reference
__device__ __forceinline__ void contract3(float x, float y, float z,
                                          float& cx, float& cy, float& cz) {
    float ax = fabsf(x), ay = fabsf(y), az = fabsf(z);
    float mag = fmaxf(ax, fmaxf(ay, az));
    int idx = (ax >= ay && ax >= az) ? 0 : ((ay >= az) ? 1 : 2);
    float inv = frcp(mag);
    float ss = (2.0f - inv) * inv;
    float sx = (idx == 0) ? ss : inv;
    float sy = (idx == 1) ? ss : inv;
    float sz = (idx == 2) ? ss : inv;
    if (mag < 1.0f) { cx = x; cy = y; cz = z; }
    else            { cx = x * sx; cy = y * sy; cz = z * sz; }
}
__device__ __forceinline__ float ugrid(int i) {
    return ((float)i + 0.5f) * (1.0f / 65.0f);
}

__global__ __launch_bounds__(WPB * 32, 5)
void nerf_render_kernel(const float* __restrict__ rays_o,
                        const float* __restrict__ rays_d,
                        const float* __restrict__ aabb,
                        const float* __restrict__ sig_c,
                        const float* __restrict__ sig_f,
                        const float* __restrict__ colors,
                        const float* __restrict__ w_view,
                        const float* __restrict__ b_view,
                        float* __restrict__ out) {
    __shared__ float   s_cw [WPB][T0 + 1];
    __shared__ uint8_t s_ind[WPB][T1 + 4];
    __shared__ float   s_b1 [WPB][T1 + 1];
    __shared__ float   s_rb1[WPB][T1 + 1];
    __shared__ float4  s_col[WPB][T1 * 4];
    __shared__ float   s_loss[3][WPB];

    const int lane = threadIdx.x & 31;
    const int w    = threadIdx.x >> 5;
    const int ray  = blockIdx.x * WPB + w;

    // ---- prefetch colors (256 float4 per ray) into shared via cp.async ------
    {
        const float4* c4 = (const float4*)colors + (size_t)ray * 256;
        uint32_t sbase = (uint32_t)__cvta_generic_to_shared(&s_col[w][0]);
#pragma unroll
        for (int it = 0; it < 8; ++it) {
            int f = it * 32 + lane;
            asm volatile("cp.async.cg.shared.global [%0], [%1], 16;\n"
                         :: "r"(sbase + f * 16), "l"(c4 + f));
        }
        asm volatile("cp.async.commit_group;\n");
    }
    const float4 sg  = *(const float4*)(sig_c + (size_t)ray * T0 + 4 * lane);
    const float2 sgf = *(const float2*)(sig_f + (size_t)ray * T1 + 2 * lane);

    const float ox = rays_o[ray * 3 + 0], oy = rays_o[ray * 3 + 1], oz = rays_o[ray * 3 + 2];
    const float dx = rays_d[ray * 3 + 0], dy = rays_d[ray * 3 + 1], dz = rays_d[ray * 3 + 2];

    float rx = frcp(dx + 1e-15f), ry = frcp(dy + 1e-15f), rz = frcp(dz + 1e-15f);
    float t0x = (aabb[0] - ox) * rx, t1x = (aabb[3] - ox) * rx;
    float t0y = (aabb[1] - oy) * ry, t1y = (aabb[4] - oy) * ry;
    float t0z = (aabb[2] - oz) * rz, t1z = (aabb[5] - oz) * rz;
    float nearv = fmaxf(fmaxf(fminf(t0x, t1x), fminf(t0y, t1y)), fminf(t0z, t1z));
    float farv  = fminf(fminf(fmaxf(t0x, t1x), fmaxf(t0y, t1y)), fmaxf(t0z, t1z));
    bool bad = farv < nearv;
    nearv = fmaxf(bad ? 1e9f : nearv, 0.05f);
    farv  = bad ? 1e9f : farv;
    const float sn = spacing_fn(nearv), sf = spacing_fn(farv);

    // ---- Stage A: coarse transmittance; cw[k] = 1 - E_k (telescoped) --------
    float e[5];
#pragma unroll
    for (int q = 0; q < 5; q++) {
        float b = (float)(4 * lane + q) * (1.0f / 128.0f);
        e[q] = spacing_inv(sn * (1.0f - b) + sf * b);
    }
    float ds0 = (e[1] - e[0]) * sg.x;
    float ds1 = (e[2] - e[1]) * sg.y;
    float ds2 = (e[3] - e[2]) * sg.z;
    float ds3 = (e[4] - e[3]) * sg.w;
    float la0 = ds0, la1 = la0 + ds1, la2 = la1 + ds2, la3 = la2 + ds3;
    float scn = wscan_incl(la3, lane);
    float baseA = scn - la3;                 // cum ds at k = 4*lane
    float E1 = __expf(-(baseA + la0));
    float E2 = __expf(-(baseA + la1));
    float E3 = __expf(-(baseA + la2));
    float E4 = __expf(-(baseA + la3));
    float cw1v = 1.0f - E1, cw2v = 1.0f - E2, cw3v = 1.0f - E3, cw4v = 1.0f - E4;
    if (lane == 0) s_cw[w][0] = 0.0f;
    s_cw[w][4 * lane + 1] = cw1v;
    s_cw[w][4 * lane + 2] = cw2v;
    s_cw[w][4 * lane + 3] = cw3v;
    s_cw[w][4 * lane + 4] = cw4v;
    float invT;
    {
        float Elast = __shfl_sync(FULLMASK, E4, 31);
        invT = frcp((1.0f - Elast) + 0.01f * 128.0f);
    }

    // ---- Stage B1: scatter sample->bin index table (register-only) ----------
    // cdf(k) = min((cw[k] + 0.01k) * invT, 1), strictly increasing; lane
    // boundary via shfl_up of the same register bits -> bitwise-consistent,
    // gap-free write-once fill. ceil guess errs by <= 1 cell, so single-step
    // conditional fixups suffice (comparisons identical to reference's).
    {
        float cw0v = __shfl_up_sync(FULLMASK, cw4v, 1);
        if (lane == 0) cw0v = 0.0f;
        float cw_l[5] = {cw0v, cw1v, cw2v, cw3v, cw4v};
        int gq[5];
#pragma unroll
        for (int q = 0; q < 5; q++) {
            int k = 4 * lane + q;
            float c = fminf((cw_l[q] + 0.01f * (float)k) * invT, 1.0f);
            int gi = (int)ceilf(c * 65.0f - 0.5f);
            gi = gi < 0 ? 0 : (gi > 65 ? 65 : gi);
            if (gi > 0  && c <= ugrid(gi - 1)) --gi;
            if (gi < 65 && c >  ugrid(gi))     ++gi;
            gq[q] = gi;
        }
#pragma unroll
        for (int q = 0; q < 4; q++) {
            int k = 4 * lane + q;
            for (int i = gq[q]; i < gq[q + 1]; ++i) s_ind[w][i] = (uint8_t)(k + 1);
        }
        if (lane == 31) {
            for (int i = gq[4]; i < 65; ++i) s_ind[w][i] = 129;
        }
    }
    __syncwarp();   // s_cw + s_ind visible

    // ---- Stage B2: inverse-CDF interpolation (3 known trips) ----------------
    {
        auto interp = [&](int i) {
            int idx = (int)s_ind[w][i];
            int below = idx - 1;
            int above = idx > T0 ? T0 : idx;
            float u = ugrid(i);
            float c0 = fminf((s_cw[w][below] + 0.01f * (float)below) * invT, 1.0f);
            float c1 = fminf((s_cw[w][above] + 0.01f * (float)above) * invT, 1.0f);
            float t = __fdividef(u - c0, c1 - c0);
            if (isnan(t)) t = 0.0f;
            t = fminf(fmaxf(t, 0.0f), 1.0f);
            float b1v = ((float)below + t * (float)(above - below)) * (1.0f / 128.0f);
            s_b1[w][i] = b1v;
            s_rb1[w][i] = spacing_inv(sn * (1.0f - b1v) + sf * b1v);
        };
        interp(lane);
        interp(lane + 32);
        if (lane == 0) interp(64);
    }
    __syncwarp();

    // ---- Stage C: fine weights1; ws telescoped ------------------------------
    const int i0 = 2 * lane, i1 = i0 + 1;
    float r0 = s_rb1[w][i0], r1 = s_rb1[w][i1], r2 = s_rb1[w][i1 + 1];
    float dsa = (r1 - r0) * sgf.x;
    float dsb = (r2 - r1) * sgf.y;
    float lca = dsa, lcb = lca + dsb;
    float scc = wscan_incl(lcb, lane);
    float bc = scc - lcb;
    float Ea = __expf(-bc);
    float Eb = __expf(-(bc + lca));
    float Ec = __expf(-(bc + lcb));
    float w1a = fmaxf(Ea - Eb, 0.0f);
    float w1b = fmaxf(Eb - Ec, 0.0f);
    float ta = 0.5f * (r0 + r1), tb = 0.5f * (r1 + r2);

    float ws = 1.0f - __shfl_sync(FULLMASK, Ec, 31);   // sum(w1) telescoped
    float dep = w1a * ta + w1b * tb;
    float fx, fy, fz;
    {
        float cxa, cya, cza, cxb, cyb, czb;
        contract3(ox + dx * ta, oy + dy * ta, oz + dz * ta, cxa, cya, cza);
        contract3(ox + dx * tb, oy + dy * tb, oz + dz * tb, cxb, cyb, czb);
        fx = w1a * cxa + w1b * cxb;
        fy = w1a * cya + w1b * cyb;
        fz = w1a * cza + w1b * czb;
    }
    // packed reductions: (dep,fx) and (fy,fz)
    {
        unsigned long long p0 = wreduce2(pack2(dep, fx));
        unsigned long long p1 = wreduce2(pack2(fy, fz));
        unpack2(p0, dep, fx);
        unpack2(p1, fy, fz);
    }
    if (lane == 0) {
        out[3 * N_RAYS + ray] = dep;
        out[4 * N_RAYS + ray * 3 + 0] = fx;
        out[4 * N_RAYS + ray * 3 + 1] = fy;
        out[4 * N_RAYS + ray * 3 + 2] = fz;
    }

    // ---- Stage E: interlevel (proposal) loss --------------------------------
    float prop;
    {
        float bA0 = s_b1[w][i0], bA1 = s_b1[w][i1], bA2 = s_b1[w][i1 + 1];
        int ilo = (int)floorf(bA0 * 128.0f); ilo = ilo < 0 ? 0 : (ilo > 127 ? 127 : ilo);
        int ihi = (int)floorf(bA1 * 128.0f); ihi = ihi < 0 ? 0 : (ihi > 127 ? 127 : ihi);
        float wseg = s_cw[w][ihi + 1] - s_cw[w][ilo];
        float dlt = fmaxf(w1a - wseg, 0.0f);
        prop = dlt * dlt * frcp(w1a + 1e-8f);
        ilo = (int)floorf(bA1 * 128.0f); ilo = ilo < 0 ? 0 : (ilo > 127 ? 127 : ilo);
        ihi = (int)floorf(bA2 * 128.0f); ihi = ihi < 0 ? 0 : (ihi > 127 ? 127 : ihi);
        wseg = s_cw[w][ihi + 1] - s_cw[w][ilo];
        dlt = fmaxf(w1b - wseg, 0.0f);
        prop += dlt * dlt * frcp(w1b + 1e-8f);
    }

    // ---- Stage F: distortion loss; exW telescoped ---------------------------
    float uni, bi;
    {
        float bA0 = s_b1[w][i0], bA1 = s_b1[w][i1], bA2 = s_b1[w][i1 + 1];
        float inta = bA1 - bA0, intb = bA2 - bA1;
        float mida = bA0 + inta * 0.5f, midb = bA1 + intb * 0.5f;
        uni = inta * w1a * w1a + intb * w1b * w1b;
        float wma = w1a * mida, wmb = w1b * midb;
        float exW_a = 1.0f - Ea, exW_b = 1.0f - Eb;
        float lm = wma + wmb;
        float siM = wscan_incl(lm, lane);
        float exM_a = siM - lm, exM_b = exM_a + wma;
        bi = wma * exW_a - w1a * exM_a + wmb * exW_b - w1b * exM_b;
    }
    // packed reduction: (prop, uni); bi scalar
    {
        unsigned long long pu = wreduce2(pack2(prop, uni));
        unpack2(pu, prop, uni);
        bi = wreduce(bi);
    }
    if (lane == 0) {
        s_loss[0][w] = prop;
        s_loss[1][w] = uni;
        s_loss[2][w] = bi;
    }

    // ---- Stage D: colors reduction (LDS.128, weights via dual shfl) ---------
    {
        asm volatile("cp.async.wait_group 0;\n");
        __syncwarp();
        // weight for float4-index f = it*32+lane: w1[f>>2] with
        // f>>2 = 2*src + ((lane>>2)&1), src = it*4+(lane>>3).
        const int wsrc_base = lane >> 3;
        const bool use_b = (lane & 4) != 0;
        unsigned long long acc01 = 0ull, acc23 = 0ull;
#pragma unroll
        for (int it = 0; it < 8; ++it) {
            float4 cv = s_col[w][it * 32 + lane];      // single LDS.128
            int src = wsrc_base + it * 4;
            float wa = __shfl_sync(FULLMASK, w1a, src);
            float wb = __shfl_sync(FULLMASK, w1b, src);
            float wv = use_b ? wb : wa;
            unsigned long long wv2 = pack2(wv, wv);
            ffma2(acc01, pack2(cv.x, cv.y), wv2);
            ffma2(acc23, pack2(cv.z, cv.w), wv2);
        }
        float a0, a1, a2, a3;
        unpack2(acc01, a0, a1);
        unpack2(acc23, a2, a3);
        // fold through w_view (channel group g = lane&3), then butterfly
        int g = lane & 3;
        float av[4] = {a0, a1, a2, a3};
        float d0 = 0.f, d1 = 0.f, d2 = 0.f;
#pragma unroll
        for (int j = 0; j < 4; j++) {
            int c = 4 * g + j;
            d0 += av[j] * w_view[c * 3 + 0];
            d1 += av[j] * w_view[c * 3 + 1];
            d2 += av[j] * w_view[c * 3 + 2];
        }
        unsigned long long dd = wreduce2(pack2(d0, d1));
        unpack2(dd, d0, d1);
        d2 = wreduce(d2);
        if (lane < 3) {
            float dv = (lane == 0) ? d0 : ((lane == 1) ? d1 : d2);
            float im = frcp(1.0f + __expf(-(dv + b_view[lane]))) + (1.0f - ws);
            out[ray * 3 + lane] = im;
        }
    }

    // ---- cross-block loss reduction: atomics + last-block finalize ----------
    __syncthreads();
    if (threadIdx.x == 0) {
        float p = 0.f, un = 0.f, bb = 0.f;
#pragma unroll
        for (int j = 0; j < WPB; j++) {
            p  += s_loss[0][j];
            un += s_loss[1][j];
            bb += s_loss[2][j];
        }
        atomicAdd(&g_acc[0], (double)p);
        atomicAdd(&g_acc[1], (double)un);
        atomicAdd(&g_acc[2], (double)bb);
        __threadfence();
        unsigned int t = atomicAdd(&g_cnt, 1u);
        if (t == (unsigned int)(NBLOCKS - 1)) {
            double rp = atomicAdd(&g_acc[0], 0.0);
            double ru = atomicAdd(&g_acc[1], 0.0);
            double rb = atomicAdd(&g_acc[2], 0.0);
            out[7 * N_RAYS]     = (float)(rp / ((double)N_RAYS * (double)T1));
            out[7 * N_RAYS + 1] = (float)(ru / (3.0 * (double)N_RAYS) +
                                          2.0 * rb / (double)N_RAYS);
            g_acc[0] = 0.0; g_acc[1] = 0.0; g_acc[2] = 0.0;
            g_cnt = 0u;
        }
    }
}

extern "C" void kernel_launch(void* const* d_in, const int* in_sizes, int n_in,
                              void* d_out, int out_size) {
    const float* rays_o = (const float*)d_in[0];
    const float* rays_d = (const float*)d_in[1];
    const float* aabb   = (const float*)d_in[2];
    const float* sig_c  = (const float*)d_in[3];
    const float* sig_f  = (const float*)d_in[4];
    const float* colors = (const float*)d_in[5];
    const float* w_view = (const float*)d_in[6];
    const float* b_view = (const float*)d_in[7];
    float* out = (float*)d_out;

    nerf_render_kernel<<<NBLOCKS, WPB * 32>>>(
        rays_o, rays_d, aabb, sig_c, sig_f, colors, w_view, b_view, out);
}

// round 11
// speedup vs baseline: 1.9724x; 1.0194x over previous
#include <cuda_runtime.h>
#include <math.h>
#include <stdint.h>

#define N_RAYS 65536
#define T0 128
#define T1 64
#define WPB 8
#define NBLOCKS (N_RAYS / WPB)   // 8192
#define FULLMASK 0xffffffffu

// cross-block loss accumulators; zero at load, reset by last block each launch
__device__ double g_acc[3];
__device__ unsigned int g_cnt;

__device__ __forceinline__ float frcp(float x) { return __fdividef(1.0f, x); }
__device__ __forceinline__ float spacing_fn(float x) {
    return x < 1.0f ? 0.5f * x : 1.0f - 0.5f * frcp(x);
}
__device__ __forceinline__ float spacing_inv(float x) {
    return x < 0.5f ? 2.0f * x : frcp(2.0f - 2.0f * x);
}
__device__ __forceinline__ float wscan_incl(float x, int lane) {
#pragma unroll
    for (int o = 1; o < 32; o <<= 1) {
        float v = __shfl_up_sync(FULLMASK, x, o);
        if (lane >= o) x += v;
    }
    return x;
}
__device__ __forceinline__ float wreduce(float x) {
#pragma unroll
    for (int o = 16; o; o >>= 1) x += __shfl_xor_sync(FULLMASK, x, o);
    return x;
}
// ---- packed f32x2 helpers (rounding identical to scalar FADD/FFMA) ---------
__device__ __forceinline__ unsigned long long pack2(float a, float b) {
    unsigned long long r;
    asm("mov.b64 %0, {%1, %2};" : "=l"(r) : "f"(a), "f"(b));
    return r;
}
__device__ __forceinline__ void unpack2(unsigned long long v, float& a, float& b) {
    asm("mov.b64 {%0, %1}, %2;" : "=f"(a), "=f"(b) : "l"(v));
}
__device__ __forceinline__ void ffma2(unsigned long long& d,
                                      unsigned long long a,
                                      unsigned long long b) {
    asm("fma.rn.f32x2 %0, %1, %2, %0;" : "+l"(d) : "l"(a), "l"(b));
}
__device__ __forceinline__ unsigned long long wreduce2(unsigned long long x) {
#pragma unroll
    for (int o = 16; o; o >>= 1) {
        unsigned long long y = __shfl_xor_sync(FULLMASK, x, o);
        asm("add.rn.f32x2 %0, %0, %1;" : "+l"(x) : "l"(y));
    }
    return x;
}
// MERF contraction matching jnp reference
__device__ __forceinline__ void contract3(float x, float y, float z,
                                          float& cx, float& cy, float& cz) {
    float ax = fabsf(x), ay = fabsf(y), az = fabsf(z);
    float mag = fmaxf(ax, fmaxf(ay, az));
    int idx = (ax >= ay && ax >= az) ? 0 : ((ay >= az) ? 1 : 2);
    float inv = frcp(mag);
    float ss = (2.0f - inv) * inv;
    float sx = (idx == 0) ? ss : inv;
    float sy = (idx == 1) ? ss : inv;
    float sz = (idx == 2) ? ss : inv;
    if (mag < 1.0f) { cx = x; cy = y; cz = z; }
    else            { cx = x * sx; cy = y * sy; cz = z * sz; }
}
__device__ __forceinline__ float ugrid(int i) {
    return ((float)i + 0.5f) * (1.0f / 65.0f);
}

__global__ __launch_bounds__(WPB * 32, 6)
void nerf_render_kernel(const float* __restrict__ rays_o,
                        const float* __restrict__ rays_d,
                        const float* __restrict__ aabb,
                        const float* __restrict__ sig_c,
                        const float* __restrict__ sig_f,
                        const float* __restrict__ colors,
                        const float* __restrict__ w_view,
                        const float* __restrict__ b_view,
                        float* __restrict__ out) {
    __shared__ float   s_cw [WPB][T0 + 1];
    __shared__ uint8_t s_ind[WPB][T1 + 4];
    __shared__ float   s_b1 [WPB][T1 + 1];
    __shared__ float   s_rb1[WPB][T1 + 1];
    __shared__ float   s_loss[3][WPB];

    const int lane = threadIdx.x & 31;
    const int w    = threadIdx.x >> 5;
    const int ray  = blockIdx.x * WPB + w;

    const float4 sg  = *(const float4*)(sig_c + (size_t)ray * T0 + 4 * lane);
    const float2 sgf = *(const float2*)(sig_f + (size_t)ray * T1 + 2 * lane);

    const float ox = rays_o[ray * 3 + 0], oy = rays_o[ray * 3 + 1], oz = rays_o[ray * 3 + 2];
    const float dx = rays_d[ray * 3 + 0], dy = rays_d[ray * 3 + 1], dz = rays_d[ray * 3 + 2];

    float rx = frcp(dx + 1e-15f), ry = frcp(dy + 1e-15f), rz = frcp(dz + 1e-15f);
    float t0x = (aabb[0] - ox) * rx, t1x = (aabb[3] - ox) * rx;
    float t0y = (aabb[1] - oy) * ry, t1y = (aabb[4] - oy) * ry;
    float t0z = (aabb[2] - oz) * rz, t1z = (aabb[5] - oz) * rz;
    float nearv = fmaxf(fmaxf(fminf(t0x, t1x), fminf(t0y, t1y)), fminf(t0z, t1z));
    float farv  = fminf(fminf(fmaxf(t0x, t1x), fmaxf(t0y, t1y)), fmaxf(t0z, t1z));
    bool bad = farv < nearv;
    nearv = fmaxf(bad ? 1e9f : nearv, 0.05f);
    farv  = bad ? 1e9f : farv;
    const float sn = spacing_fn(nearv), sf = spacing_fn(farv);

    // ---- Stage A: coarse transmittance; cw[k] = 1 - E_k (telescoped) --------
    float e[5];
#pragma unroll
    for (int q = 0; q < 5; q++) {
        float b = (float)(4 * lane + q) * (1.0f / 128.0f);
        e[q] = spacing_inv(sn * (1.0f - b) + sf * b);
    }
    float ds0 = (e[1] - e[0]) * sg.x;
    float ds1 = (e[2] - e[1]) * sg.y;
    float ds2 = (e[3] - e[2]) * sg.z;
    float ds3 = (e[4] - e[3]) * sg.w;
    float la0 = ds0, la1 = la0 + ds1, la2 = la1 + ds2, la3 = la2 + ds3;
    float scn = wscan_incl(la3, lane);
    float baseA = scn - la3;                 // cum ds at k = 4*lane
    float E1 = __expf(-(baseA + la0));
    float E2 = __expf(-(baseA + la1));
    float E3 = __expf(-(baseA + la2));
    float E4 = __expf(-(baseA + la3));
    float cw1v = 1.0f - E1, cw2v = 1.0f - E2, cw3v = 1.0f - E3, cw4v = 1.0f - E4;
    if (lane == 0) s_cw[w][0] = 0.0f;
    s_cw[w][4 * lane + 1] = cw1v;
    s_cw[w][4 * lane + 2] = cw2v;
    s_cw[w][4 * lane + 3] = cw3v;
    s_cw[w][4 * lane + 4] = cw4v;
    float invT;
    {
        float Elast = __shfl_sync(FULLMASK, E4, 31);
        invT = frcp((1.0f - Elast) + 0.01f * 128.0f);
    }

    // ---- Stage B1: scatter sample->bin index table (register-only) ----------
    // cdf(k) = min((cw[k] + 0.01k) * invT, 1), strictly increasing; lane
    // boundary via shfl_up of the same register bits -> bitwise-consistent,
    // gap-free write-once fill. ceil guess errs by <= 1 cell.
    {
        float cw0v = __shfl_up_sync(FULLMASK, cw4v, 1);
        if (lane == 0) cw0v = 0.0f;
        float cw_l[5] = {cw0v, cw1v, cw2v, cw3v, cw4v};
        int gq[5];
#pragma unroll
        for (int q = 0; q < 5; q++) {
            int k = 4 * lane + q;
            float c = fminf((cw_l[q] + 0.01f * (float)k) * invT, 1.0f);
            int gi = (int)ceilf(c * 65.0f - 0.5f);
            gi = gi < 0 ? 0 : (gi > 65 ? 65 : gi);
            if (gi > 0  && c <= ugrid(gi - 1)) --gi;
            if (gi < 65 && c >  ugrid(gi))     ++gi;
            gq[q] = gi;
        }
#pragma unroll
        for (int q = 0; q < 4; q++) {
            int k = 4 * lane + q;
            for (int i = gq[q]; i < gq[q + 1]; ++i) s_ind[w][i] = (uint8_t)(k + 1);
        }
        if (lane == 31) {
            for (int i = gq[4]; i < 65; ++i) s_ind[w][i] = 129;
        }
    }
    __syncwarp();   // s_cw + s_ind visible

    // ---- Stage B2: inverse-CDF interpolation (3 known trips) ----------------
    {
        auto interp = [&](int i) {
            int idx = (int)s_ind[w][i];
            int below = idx - 1;
            int above = idx > T0 ? T0 : idx;
            float u = ugrid(i);
            float c0 = fminf((s_cw[w][below] + 0.01f * (float)below) * invT, 1.0f);
            float c1 = fminf((s_cw[w][above] + 0.01f * (float)above) * invT, 1.0f);
            float t = __fdividef(u - c0, c1 - c0);
            if (isnan(t)) t = 0.0f;
            t = fminf(fmaxf(t, 0.0f), 1.0f);
            float b1v = ((float)below + t * (float)(above - below)) * (1.0f / 128.0f);
            s_b1[w][i] = b1v;
            s_rb1[w][i] = spacing_inv(sn * (1.0f - b1v) + sf * b1v);
        };
        interp(lane);
        interp(lane + 32);
        if (lane == 0) interp(64);
    }
    __syncwarp();

    // ---- Stage C: fine weights1; ws telescoped ------------------------------
    const int i0 = 2 * lane, i1 = i0 + 1;
    float r0 = s_rb1[w][i0], r1 = s_rb1[w][i1], r2 = s_rb1[w][i1 + 1];
    float dsa = (r1 - r0) * sgf.x;
    float dsb = (r2 - r1) * sgf.y;
    float lca = dsa, lcb = lca + dsb;
    float scc = wscan_incl(lcb, lane);
    float bc = scc - lcb;
    float Ea = __expf(-bc);
    float Eb = __expf(-(bc + lca));
    float Ec = __expf(-(bc + lcb));
    float w1a = fmaxf(Ea - Eb, 0.0f);
    float w1b = fmaxf(Eb - Ec, 0.0f);
    float ta = 0.5f * (r0 + r1), tb = 0.5f * (r1 + r2);

    float ws = 1.0f - __shfl_sync(FULLMASK, Ec, 31);   // sum(w1) telescoped
    float dep = w1a * ta + w1b * tb;
    float fx, fy, fz;
    {
        float cxa, cya, cza, cxb, cyb, czb;
        contract3(ox + dx * ta, oy + dy * ta, oz + dz * ta, cxa, cya, cza);
        contract3(ox + dx * tb, oy + dy * tb, oz + dz * tb, cxb, cyb, czb);
        fx = w1a * cxa + w1b * cxb;
        fy = w1a * cya + w1b * cyb;
        fz = w1a * cza + w1b * czb;
    }
    // packed reductions: (dep,fx) and (fy,fz)
    {
        unsigned long long p0 = wreduce2(pack2(dep, fx));
        unsigned long long p1 = wreduce2(pack2(fy, fz));
        unpack2(p0, dep, fx);
        unpack2(p1, fy, fz);
    }
    if (lane == 0) {
        out[3 * N_RAYS + ray] = dep;
        out[4 * N_RAYS + ray * 3 + 0] = fx;
        out[4 * N_RAYS + ray * 3 + 1] = fy;
        out[4 * N_RAYS + ray * 3 + 2] = fz;
    }

    // ---- Stage E: interlevel (proposal) loss --------------------------------
    float prop;
    {
        float bA0 = s_b1[w][i0], bA1 = s_b1[w][i1], bA2 = s_b1[w][i1 + 1];
        int ilo = (int)floorf(bA0 * 128.0f); ilo = ilo < 0 ? 0 : (ilo > 127 ? 127 : ilo);
        int ihi = (int)floorf(bA1 * 128.0f); ihi = ihi < 0 ? 0 : (ihi > 127 ? 127 : ihi);
        float wseg = s_cw[w][ihi + 1] - s_cw[w][ilo];
        float dlt = fmaxf(w1a - wseg, 0.0f);
        prop = dlt * dlt * frcp(w1a + 1e-8f);
        ilo = (int)floorf(bA1 * 128.0f); ilo = ilo < 0 ? 0 : (ilo > 127 ? 127 : ilo);
        ihi = (int)floorf(bA2 * 128.0f); ihi = ihi < 0 ? 0 : (ihi > 127 ? 127 : ihi);
        wseg = s_cw[w][ihi + 1] - s_cw[w][ilo];
        dlt = fmaxf(w1b - wseg, 0.0f);
        prop += dlt * dlt * frcp(w1b + 1e-8f);
    }

    // ---- Stage F: distortion loss; exW telescoped ---------------------------
    float uni, bi;
    {
        float bA0 = s_b1[w][i0], bA1 = s_b1[w][i1], bA2 = s_b1[w][i1 + 1];
        float inta = bA1 - bA0, intb = bA2 - bA1;
        float mida = bA0 + inta * 0.5f, midb = bA1 + intb * 0.5f;
        uni = inta * w1a * w1a + intb * w1b * w1b;
        float wma = w1a * mida, wmb = w1b * midb;
        float exW_a = 1.0f - Ea, exW_b = 1.0f - Eb;
        float lm = wma + wmb;
        float siM = wscan_incl(lm, lane);
        float exM_a = siM - lm, exM_b = exM_a + wma;
        bi = wma * exW_a - w1a * exM_a + wmb * exW_b - w1b * exM_b;
    }
    // packed reduction: (prop, uni); bi scalar
    {
        unsigned long long pu = wreduce2(pack2(prop, uni));
        unpack2(pu, prop, uni);
        bi = wreduce(bi);
    }
    if (lane == 0) {
        s_loss[0][w] = prop;
        s_loss[1][w] = uni;
        s_loss[2][w] = bi;
    }

    // ---- Stage D: colors reduction (direct streaming LDG.128) ---------------
    {
        // weight for float4-index f = it*32+lane: w1[f>>2] with
        // f>>2 = 2*src + ((lane>>2)&1), src = it*4+(lane>>3).
        const float4* c4 = (const float4*)colors + (size_t)ray * 256;
        const int wsrc_base = lane >> 3;
        const bool use_b = (lane & 4) != 0;
        unsigned long long acc01 = 0ull, acc23 = 0ull;
#pragma unroll
        for (int it = 0; it < 8; ++it) {
            float4 cv = __ldcs(c4 + it * 32 + lane);   // streaming LDG.128
            int src = wsrc_base + it * 4;
            float wa = __shfl_sync(FULLMASK, w1a, src);
            float wb = __shfl_sync(FULLMASK, w1b, src);
            float wv = use_b ? wb : wa;
            unsigned long long wv2 = pack2(wv, wv);
            ffma2(acc01, pack2(cv.x, cv.y), wv2);
            ffma2(acc23, pack2(cv.z, cv.w), wv2);
        }
        float a0, a1, a2, a3;
        unpack2(acc01, a0, a1);
        unpack2(acc23, a2, a3);
        // fold through w_view (channel group g = lane&3), then butterfly
        int g = lane & 3;
        float av[4] = {a0, a1, a2, a3};
        float d0 = 0.f, d1 = 0.f, d2 = 0.f;
#pragma unroll
        for (int j = 0; j < 4; j++) {
            int c = 4 * g + j;
            d0 += av[j] * w_view[c * 3 + 0];
            d1 += av[j] * w_view[c * 3 + 1];
            d2 += av[j] * w_view[c * 3 + 2];
        }
        unsigned long long dd = wreduce2(pack2(d0, d1));
        unpack2(dd, d0, d1);
        d2 = wreduce(d2);
        if (lane < 3) {
            float dv = (lane == 0) ? d0 : ((lane == 1) ? d1 : d2);
            float im = frcp(1.0f + __expf(-(dv + b_view[lane]))) + (1.0f - ws);
            out[ray * 3 + lane] = im;
        }
    }

    // ---- cross-block loss reduction: atomics + last-block finalize ----------
    __syncthreads();
    if (threadIdx.x == 0) {
        float p = 0.f, un = 0.f, bb = 0.f;
#pragma unroll
        for (int j = 0; j < WPB; j++) {
            p  += s_loss[0][j];
            un += s_loss[1][j];
            bb += s_loss[2][j];
        }
        atomicAdd(&g_acc[0], (double)p);
        atomicAdd(&g_acc[1], (double)un);
        atomicAdd(&g_acc[2], (double)bb);
        __threadfence();
        unsigned int t = atomicAdd(&g_cnt, 1u);
        if (t == (unsigned int)(NBLOCKS - 1)) {
            double rp = atomicAdd(&g_acc[0], 0.0);
            double ru = atomicAdd(&g_acc[1], 0.0);
            double rb = atomicAdd(&g_acc[2], 0.0);
            out[7 * N_RAYS]     = (float)(rp / ((double)N_RAYS * (double)T1));
            out[7 * N_RAYS + 1] = (float)(ru / (3.0 * (double)N_RAYS) +
                                          2.0 * rb / (double)N_RAYS);
            g_acc[0] = 0.0; g_acc[1] = 0.0; g_acc[2] = 0.0;
            g_cnt = 0u;
        }
    }
}

extern "C" void kernel_launch(void* const* d_in, const int* in_sizes, int n_in,
                              void* d_out, int out_size) {
    const float* rays_o = (const float*)d_in[0];
    const float* rays_d = (const float*)d_in[1];
    const float* aabb   = (const float*)d_in[2];
    const float* sig_c  = (const float*)d_in[3];
    const float* sig_f  = (const float*)d_in[4];
    const float* colors = (const float*)d_in[5];
    const float* w_view = (const float*)d_in[6];
    const float* b_view = (const float*)d_in[7];
    float* out = (float*)d_out;

    nerf_render_kernel<<<NBLOCKS, WPB * 32>>>(
        rays_o, rays_d, aabb, sig_c, sig_f, colors, w_view, b_view, out);
}

// round 14
// speedup vs baseline: 2.0867x; 1.0579x over previous
#include <cuda_runtime.h>
#include <math.h>
#include <stdint.h>

#define N_RAYS 65536
#define T0 128
#define T1 64
#define WPB 8
#define NBLOCKS (N_RAYS / WPB)   // 8192
#define FULLMASK 0xffffffffu

// cross-block loss accumulators; zero at load, reset by last block each launch
__device__ double g_acc[3];
__device__ unsigned int g_cnt;

__device__ __forceinline__ float frcp(float x) { return __fdividef(1.0f, x); }
__device__ __forceinline__ float spacing_fn(float x) {
    return x < 1.0f ? 0.5f * x : 1.0f - 0.5f * frcp(x);
}
__device__ __forceinline__ float spacing_inv(float x) {
    return x < 0.5f ? 2.0f * x : frcp(2.0f - 2.0f * x);
}
__device__ __forceinline__ float wscan_incl(float x, int lane) {
#pragma unroll
    for (int o = 1; o < 32; o <<= 1) {
        float v = __shfl_up_sync(FULLMASK, x, o);
        if (lane >= o) x += v;
    }
    return x;
}
__device__ __forceinline__ float wreduce(float x) {
#pragma unroll
    for (int o = 16; o; o >>= 1) x += __shfl_xor_sync(FULLMASK, x, o);
    return x;
}
// ---- packed f32x2 helpers (rounding identical to scalar FADD/FFMA) ---------
__device__ __forceinline__ unsigned long long pack2(float a, float b) {
    unsigned long long r;
    asm("mov.b64 %0, {%1, %2};" : "=l"(r) : "f"(a), "f"(b));
    return r;
}
__device__ __forceinline__ void unpack2(unsigned long long v, float& a, float& b) {
    asm("mov.b64 {%0, %1}, %2;" : "=f"(a), "=f"(b) : "l"(v));
}
__device__ __forceinline__ void ffma2(unsigned long long& d,
                                      unsigned long long a,
                                      unsigned long long b) {
    asm("fma.rn.f32x2 %0, %1, %2, %0;" : "+l"(d) : "l"(a), "l"(b));
}
__device__ __forceinline__ unsigned long long wreduce2(unsigned long long x) {
#pragma unroll
    for (int o = 16; o; o >>= 1) {
        unsigned long long y = __shfl_xor_sync(FULLMASK, x, o);
        asm("add.rn.f32x2 %0, %0, %1;" : "+l"(x) : "l"(y));
    }
    return x;
}
// MERF contraction matching jnp reference
__device__ __forceinline__ void contract3(float x, float y, float z,
                                          float& cx, float& cy, float& cz) {
    float ax = fabsf(x), ay = fabsf(y), az = fabsf(z);
    float mag = fmaxf(ax, fmaxf(ay, az));
    int idx = (ax >= ay && ax >= az) ? 0 : ((ay >= az) ? 1 : 2);
    float inv = frcp(mag);
    float ss = (2.0f - inv) * inv;
    float sx = (idx == 0) ? ss : inv;
    float sy = (idx == 1) ? ss : inv;
    float sz = (idx == 2) ? ss : inv;
    if (mag < 1.0f) { cx = x; cy = y; cz = z; }
    else            { cx = x * sx; cy = y * sy; cz = z * sz; }
}
__device__ __forceinline__ float ugrid(int i) {
    return ((float)i + 0.5f) * (1.0f / 65.0f);
}

__global__ __launch_bounds__(WPB * 32, 6)
void nerf_render_kernel(const float* __restrict__ rays_o,
                        const float* __restrict__ rays_d,
                        const float* __restrict__ aabb,
                        const float* __restrict__ sig_c,
                        const float* __restrict__ sig_f,
                        const float* __restrict__ colors,
                        const float* __restrict__ w_view,
                        const float* __restrict__ b_view,
                        float* __restrict__ out) {
    __shared__ float2  s_cwp[WPB][T0 + 1];   // {cw[k], cw[k+1]}
    __shared__ uint8_t s_ind[WPB][T1 + 4];
    __shared__ float2  s_brb[WPB][T1 + 1];   // {b1, rb1}
    __shared__ float   s_w1 [WPB][T1];
    __shared__ float   s_loss[3][WPB];

    const int lane = threadIdx.x & 31;
    const int w    = threadIdx.x >> 5;
    const int ray  = blockIdx.x * WPB + w;

    const float4 sg  = *(const float4*)(sig_c + (size_t)ray * T0 + 4 * lane);
    const float2 sgf = *(const float2*)(sig_f + (size_t)ray * T1 + 2 * lane);

    const float ox = rays_o[ray * 3 + 0], oy = rays_o[ray * 3 + 1], oz = rays_o[ray * 3 + 2];
    const float dx = rays_d[ray * 3 + 0], dy = rays_d[ray * 3 + 1], dz = rays_d[ray * 3 + 2];

    float rx = frcp(dx + 1e-15f), ry = frcp(dy + 1e-15f), rz = frcp(dz + 1e-15f);
    float t0x = (aabb[0] - ox) * rx, t1x = (aabb[3] - ox) * rx;
    float t0y = (aabb[1] - oy) * ry, t1y = (aabb[4] - oy) * ry;
    float t0z = (aabb[2] - oz) * rz, t1z = (aabb[5] - oz) * rz;
    float nearv = fmaxf(fmaxf(fminf(t0x, t1x), fminf(t0y, t1y)), fminf(t0z, t1z));
    float farv  = fminf(fminf(fmaxf(t0x, t1x), fmaxf(t0y, t1y)), fmaxf(t0z, t1z));
    bool bad = farv < nearv;
    nearv = fmaxf(bad ? 1e9f : nearv, 0.05f);
    farv  = bad ? 1e9f : farv;
    const float sn = spacing_fn(nearv), sf = spacing_fn(farv);

    // ---- Stage A: coarse transmittance; cw[k] = 1 - E_k (telescoped) --------
    float e[5];
#pragma unroll
    for (int q = 0; q < 5; q++) {
        float b = (float)(4 * lane + q) * (1.0f / 128.0f);
        e[q] = spacing_inv(sn * (1.0f - b) + sf * b);
    }
    float ds0 = (e[1] - e[0]) * sg.x;
    float ds1 = (e[2] - e[1]) * sg.y;
    float ds2 = (e[3] - e[2]) * sg.z;
    float ds3 = (e[4] - e[3]) * sg.w;
    float la0 = ds0, la1 = la0 + ds1, la2 = la1 + ds2, la3 = la2 + ds3;
    float scn = wscan_incl(la3, lane);
    float baseA = scn - la3;                 // cum ds at k = 4*lane
    float E1 = __expf(-(baseA + la0));
    float E2 = __expf(-(baseA + la1));
    float E3 = __expf(-(baseA + la2));
    float E4 = __expf(-(baseA + la3));
    float cw1v = 1.0f - E1, cw2v = 1.0f - E2, cw3v = 1.0f - E3, cw4v = 1.0f - E4;
    float cw0v = __shfl_up_sync(FULLMASK, cw4v, 1);
    if (lane == 0) cw0v = 0.0f;
    // pair store: s_cwp[k] = {cw[k], cw[k+1]} (4 STS.64 per lane)
    s_cwp[w][4 * lane + 0] = make_float2(cw0v, cw1v);
    s_cwp[w][4 * lane + 1] = make_float2(cw1v, cw2v);
    s_cwp[w][4 * lane + 2] = make_float2(cw2v, cw3v);
    s_cwp[w][4 * lane + 3] = make_float2(cw3v, cw4v);
    if (lane == 31) s_cwp[w][T0] = make_float2(cw4v, cw4v);  // paranoia slot
    float invT;
    {
        float Elast = __shfl_sync(FULLMASK, E4, 31);
        invT = frcp((1.0f - Elast) + 0.01f * 128.0f);
    }

    // ---- Stage B1: scatter sample->bin index table (register-only) ----------
    // cdf(k) = min((cw[k] + 0.01k) * invT, 1), strictly increasing; lane
    // boundary via shfl_up of the same register bits -> bitwise-consistent,
    // gap-free write-once fill. ceil guess errs by <= 1 cell.
    {
        float cw_l[5] = {cw0v, cw1v, cw2v, cw3v, cw4v};
        int gq[5];
#pragma unroll
        for (int q = 0; q < 5; q++) {
            int k = 4 * lane + q;
            float c = fminf((cw_l[q] + 0.01f * (float)k) * invT, 1.0f);
            int gi = (int)ceilf(c * 65.0f - 0.5f);
            gi = gi < 0 ? 0 : (gi > 65 ? 65 : gi);
            if (gi > 0  && c <= ugrid(gi - 1)) --gi;
            if (gi < 65 && c >  ugrid(gi))     ++gi;
            gq[q] = gi;
        }
#pragma unroll
        for (int q = 0; q < 4; q++) {
            int k = 4 * lane + q;
            for (int i = gq[q]; i < gq[q + 1]; ++i) s_ind[w][i] = (uint8_t)(k + 1);
        }
        if (lane == 31) {
            for (int i = gq[4]; i < 65; ++i) s_ind[w][i] = 129;  // unreachable
        }
    }
    __syncwarp();   // s_cwp + s_ind visible

    // ---- Stage B2: inverse-CDF interpolation (3 known trips) ----------------
    // above == below+1 always (cdf(128)~1 > all u), so one pair LDS.64 gives
    // both cdf endpoints.
    {
        auto interp = [&](int i) {
            int below = (int)s_ind[w][i] - 1;
            float2 cp = s_cwp[w][below];
            float u = ugrid(i);
            float c0 = fminf((cp.x + 0.01f * (float)below) * invT, 1.0f);
            float c1 = fminf((cp.y + 0.01f * (float)(below + 1)) * invT, 1.0f);
            float t = __fdividef(u - c0, c1 - c0);
            if (isnan(t)) t = 0.0f;
            t = fminf(fmaxf(t, 0.0f), 1.0f);
            float b1v = ((float)below + t) * (1.0f / 128.0f);
            s_brb[w][i] = make_float2(b1v, spacing_inv(sn * (1.0f - b1v) + sf * b1v));
        };
        interp(lane);
        interp(lane + 32);
        if (lane == 0) interp(64);
    }
    __syncwarp();

    // ---- Stage C: fine weights1; ws telescoped ------------------------------
    const int i0 = 2 * lane, i1 = i0 + 1;
    float2 p0 = s_brb[w][i0], p1 = s_brb[w][i1], p2 = s_brb[w][i1 + 1];
    float r0 = p0.y, r1 = p1.y, r2 = p2.y;
    float bA0 = p0.x, bA1 = p1.x, bA2 = p2.x;
    float dsa = (r1 - r0) * sgf.x;
    float dsb = (r2 - r1) * sgf.y;
    float lca = dsa, lcb = lca + dsb;
    float scc = wscan_incl(lcb, lane);
    float bc = scc - lcb;
    float Ea = __expf(-bc);
    float Eb = __expf(-(bc + lca));
    float Ec = __expf(-(bc + lcb));
    float w1a = fmaxf(Ea - Eb, 0.0f);
    float w1b = fmaxf(Eb - Ec, 0.0f);
    *(float2*)&s_w1[w][i0] = make_float2(w1a, w1b);     // one STS.64
    float ta = 0.5f * (r0 + r1), tb = 0.5f * (r1 + r2);

    float ws = 1.0f - __shfl_sync(FULLMASK, Ec, 31);   // sum(w1) telescoped
    float dep = w1a * ta + w1b * tb;
    float fx, fy, fz;
    {
        float cxa, cya, cza, cxb, cyb, czb;
        contract3(ox + dx * ta, oy + dy * ta, oz + dz * ta, cxa, cya, cza);
        contract3(ox + dx * tb, oy + dy * tb, oz + dz * tb, cxb, cyb, czb);
        fx = w1a * cxa + w1b * cxb;
        fy = w1a * cya + w1b * cyb;
        fz = w1a * cza + w1b * czb;
    }
    // packed reductions: (dep,fx) and (fy,fz)
    {
        unsigned long long q0 = wreduce2(pack2(dep, fx));
        unsigned long long q1 = wreduce2(pack2(fy, fz));
        unpack2(q0, dep, fx);
        unpack2(q1, fy, fz);
    }
    if (lane == 0) {
        out[3 * N_RAYS + ray] = dep;
        out[4 * N_RAYS + ray * 3 + 0] = fx;
        out[4 * N_RAYS + ray * 3 + 1] = fy;
        out[4 * N_RAYS + ray * 3 + 2] = fz;
    }

    // ---- Stage E: interlevel (proposal) loss --------------------------------
    float prop;
    {
        int ilo = (int)floorf(bA0 * 128.0f); ilo = ilo < 0 ? 0 : (ilo > 127 ? 127 : ilo);
        int ihi = (int)floorf(bA1 * 128.0f); ihi = ihi < 0 ? 0 : (ihi > 127 ? 127 : ihi);
        float wseg = s_cwp[w][ihi].y - s_cwp[w][ilo].x;   // cw[ihi+1] - cw[ilo]
        float dlt = fmaxf(w1a - wseg, 0.0f);
        prop = dlt * dlt * frcp(w1a + 1e-8f);
        ilo = (int)floorf(bA1 * 128.0f); ilo = ilo < 0 ? 0 : (ilo > 127 ? 127 : ilo);
        ihi = (int)floorf(bA2 * 128.0f); ihi = ihi < 0 ? 0 : (ihi > 127 ? 127 : ihi);
        wseg = s_cwp[w][ihi].y - s_cwp[w][ilo].x;
        dlt = fmaxf(w1b - wseg, 0.0f);
        prop += dlt * dlt * frcp(w1b + 1e-8f);
    }

    // ---- Stage F: distortion loss; exW telescoped ---------------------------
    float uni, bi;
    {
        float inta = bA1 - bA0, intb = bA2 - bA1;
        float mida = bA0 + inta * 0.5f, midb = bA1 + intb * 0.5f;
        uni = inta * w1a * w1a + intb * w1b * w1b;
        float wma = w1a * mida, wmb = w1b * midb;
        float exW_a = 1.0f - Ea, exW_b = 1.0f - Eb;
        float lm = wma + wmb;
        float siM = wscan_incl(lm, lane);
        float exM_a = siM - lm, exM_b = exM_a + wma;
        bi = wma * exW_a - w1a * exM_a + wmb * exW_b - w1b * exM_b;
    }
    // packed reduction: (prop, uni); bi scalar
    {
        unsigned long long pu = wreduce2(pack2(prop, uni));
        unpack2(pu, prop, uni);
        bi = wreduce(bi);
    }
    if (lane == 0) {
        s_loss[0][w] = prop;
        s_loss[1][w] = uni;
        s_loss[2][w] = bi;
    }
    __syncwarp();   // s_w1 visible for stage D

    // ---- Stage D: colors reduction (LDG.128 stream + s_w1 broadcast LDS) ----
    {
        // weight for float4-index f = it*32+lane: w1[f>>2], f>>2 = it*8+(lane>>2)
        const float4* c4 = (const float4*)colors + (size_t)ray * 256;
        const int woff = lane >> 2;
        unsigned long long acc01 = 0ull, acc23 = 0ull;
#pragma unroll
        for (int it = 0; it < 8; ++it) {
            float4 cv = __ldcs(c4 + it * 32 + lane);   // streaming LDG.128
            float wv = s_w1[w][it * 8 + woff];         // broadcast LDS.32
            unsigned long long wv2 = pack2(wv, wv);
            ffma2(acc01, pack2(cv.x, cv.y), wv2);
            ffma2(acc23, pack2(cv.z, cv.w), wv2);
        }
        float a0, a1, a2, a3;
        unpack2(acc01, a0, a1);
        unpack2(acc23, a2, a3);
        // fold through w_view (channel group g = lane&3), then butterfly
        int g = lane & 3;
        float av[4] = {a0, a1, a2, a3};
        float d0 = 0.f, d1 = 0.f, d2 = 0.f;
#pragma unroll
        for (int j = 0; j < 4; j++) {
            int c = 4 * g + j;
            d0 += av[j] * w_view[c * 3 + 0];
            d1 += av[j] * w_view[c * 3 + 1];
            d2 += av[j] * w_view[c * 3 + 2];
        }
        unsigned long long dd = wreduce2(pack2(d0, d1));
        unpack2(dd, d0, d1);
        d2 = wreduce(d2);
        if (lane < 3) {
            float dv = (lane == 0) ? d0 : ((lane == 1) ? d1 : d2);
            float im = frcp(1.0f + __expf(-(dv + b_view[lane]))) + (1.0f - ws);
            out[ray * 3 + lane] = im;
        }
    }

    // ---- cross-block loss reduction: atomics + last-block finalize ----------
    __syncthreads();
    if (threadIdx.x == 0) {
        float p = 0.f, un = 0.f, bb = 0.f;
#pragma unroll
        for (int j = 0; j < WPB; j++) {
            p  += s_loss[0][j];
            un += s_loss[1][j];
            bb += s_loss[2][j];
        }
        atomicAdd(&g_acc[0], (double)p);
        atomicAdd(&g_acc[1], (double)un);
        atomicAdd(&g_acc[2], (double)bb);
        __threadfence();
        unsigned int t = atomicAdd(&g_cnt, 1u);
        if (t == (unsigned int)(NBLOCKS - 1)) {
            double rp = atomicAdd(&g_acc[0], 0.0);
            double ru = atomicAdd(&g_acc[1], 0.0);
            double rb = atomicAdd(&g_acc[2], 0.0);
            out[7 * N_RAYS]     = (float)(rp / ((double)N_RAYS * (double)T1));
            out[7 * N_RAYS + 1] = (float)(ru / (3.0 * (double)N_RAYS) +
                                          2.0 * rb / (double)N_RAYS);
            g_acc[0] = 0.0; g_acc[1] = 0.0; g_acc[2] = 0.0;
            g_cnt = 0u;
        }
    }
}

extern "C" void kernel_launch(void* const* d_in, const int* in_sizes, int n_in,
                              void* d_out, int out_size) {
    const float* rays_o = (const float*)d_in[0];
    const float* rays_d = (const float*)d_in[1];
    const float* aabb   = (const float*)d_in[2];
    const float* sig_c  = (const float*)d_in[3];
    const float* sig_f  = (const float*)d_in[4];
    const float* colors = (const float*)d_in[5];
    const float* w_view = (const float*)d_in[6];
    const float* b_view = (const float*)d_in[7];
    float* out = (float*)d_out;

    nerf_render_kernel<<<NBLOCKS, WPB * 32>>>(
        rays_o, rays_d, aabb, sig_c, sig_f, colors, w_view, b_view, out);
}